// round 1
// baseline (speedup 1.0000x reference)
#include <cuda_runtime.h>
#include <math.h>

// ---------------- problem constants ----------------
#define TOK    8192        // B*N
#define CDIM   768
#define HNUM   12
#define HDIM   64
#define NSEQ   1024
#define BATCH  8
#define MLPH   3072
#define QKVW   6912        // 3 stages * 3*C, fused qkv gemm output width
#define STAGES 3

constexpr long TOKC   = (long)TOK * CDIM;          // 6,291,456
constexpr long OFF_H   = 0;
constexpr long OFF_QKV = OFF_H   + TOKC;           // h        [TOK, C]
constexpr long OFF_O   = OFF_QKV + (long)TOK*QKVW; // qkv      [TOK, 6912]
constexpr long OFF_P   = OFF_O   + 3*TOKC;         // attn o   [3, TOK, C]
constexpr long OFF_X1  = OFF_P   + 3*TOKC;         // proj out [3, TOK, C]
constexpr long OFF_H2  = OFF_X1  + TOKC;           // x1       [TOK, C]
constexpr long OFF_G   = OFF_H2  + TOKC;           // h2       [TOK, C]
constexpr long ARENA_SZ = OFF_G  + (long)TOK*MLPH; // gelu out [TOK, 3072]

__device__ float g_arena[ARENA_SZ];                // ~554 MB static scratch

// ---------------- layernorm ----------------
__global__ void ln_kernel(const float* __restrict__ xext, long xOff,
                          const float* __restrict__ w, const float* __restrict__ b,
                          long outOff)
{
    int row = blockIdx.x;
    const float* xr = (xext ? xext : (const float*)(g_arena + xOff)) + (long)row * CDIM;
    int t = threadIdx.x;            // 256 threads, 3 elems each
    float v0 = xr[t], v1 = xr[t + 256], v2 = xr[t + 512];
    float s = v0 + v1 + v2;

    __shared__ float red[8];
    #pragma unroll
    for (int o = 16; o > 0; o >>= 1) s += __shfl_xor_sync(0xffffffffu, s, o);
    if ((t & 31) == 0) red[t >> 5] = s;
    __syncthreads();
    float tot = red[0]+red[1]+red[2]+red[3]+red[4]+red[5]+red[6]+red[7];
    float mu = tot * (1.0f / CDIM);

    float d0 = v0 - mu, d1 = v1 - mu, d2 = v2 - mu;
    float q = d0*d0 + d1*d1 + d2*d2;
    #pragma unroll
    for (int o = 16; o > 0; o >>= 1) q += __shfl_xor_sync(0xffffffffu, q, o);
    __syncthreads();
    if ((t & 31) == 0) red[t >> 5] = q;
    __syncthreads();
    float qt = red[0]+red[1]+red[2]+red[3]+red[4]+red[5]+red[6]+red[7];
    float inv = rsqrtf(qt * (1.0f / CDIM) + 1e-5f);

    float* op = g_arena + outOff + (long)row * CDIM;
    op[t      ] = d0 * inv * w[t      ] + b[t      ];
    op[t + 256] = d1 * inv * w[t + 256] + b[t + 256];
    op[t + 512] = d2 * inv * w[t + 512] + b[t + 512];
}

// ---------------- SGEMM: out[m,n] = sum_k A[m,k] * W[n,k]  (A @ W^T) ----------------
// BM=BN=128, BK=16, 256 threads, 8x8 per thread, double-buffered smem.
// MODE 0: C = acc           (into arena)
// MODE 2: C = gelu(acc + bias)      (into arena)
// MODE 3: C = res + acc + bias      (into Cext = d_out)
#define BM 128
#define BN 128
#define BKD 16

__device__ __forceinline__ float gelu_f(float v) {
    return 0.5f * v * (1.0f + erff(v * 0.70710678118654752440f));
}

template<int MODE>
__global__ __launch_bounds__(256)
void sgemm(long aOff, const float* __restrict__ Wt, long cOff, float* __restrict__ Cext,
           const float* __restrict__ bias, long resOff,
           int M, int Nout, int K, long aStride, long wStride, long cStride)
{
    const float* A = g_arena + aOff + (long)blockIdx.z * aStride;
    const float* W = Wt + (long)blockIdx.z * wStride;
    float* Cp = Cext ? Cext : (g_arena + cOff + (long)blockIdx.z * cStride);

    int n0 = blockIdx.x * BN;
    int m0 = blockIdx.y * BM;
    int tid = threadIdx.x;
    int tr = tid >> 4;          // 0..15
    int tc = tid & 15;          // 0..15

    __shared__ __align__(16) float As[2][BKD][BM];
    __shared__ __align__(16) float Bs[2][BKD][BN];

    float acc[8][8] = {};

    int r0 = tid >> 2;                 // rows 0..63
    int r1 = (tid + 256) >> 2;         // rows 64..127
    int c0 = (tid & 3) * 4;            // 0,4,8,12

    // tile 0 direct to smem
    {
        float4 va0 = *(const float4*)&A[(long)(m0 + r0) * K + c0];
        float4 va1 = *(const float4*)&A[(long)(m0 + r1) * K + c0];
        float4 vb0 = *(const float4*)&W[(long)(n0 + r0) * K + c0];
        float4 vb1 = *(const float4*)&W[(long)(n0 + r1) * K + c0];
        As[0][c0+0][r0]=va0.x; As[0][c0+1][r0]=va0.y; As[0][c0+2][r0]=va0.z; As[0][c0+3][r0]=va0.w;
        As[0][c0+0][r1]=va1.x; As[0][c0+1][r1]=va1.y; As[0][c0+2][r1]=va1.z; As[0][c0+3][r1]=va1.w;
        Bs[0][c0+0][r0]=vb0.x; Bs[0][c0+1][r0]=vb0.y; Bs[0][c0+2][r0]=vb0.z; Bs[0][c0+3][r0]=vb0.w;
        Bs[0][c0+0][r1]=vb1.x; Bs[0][c0+1][r1]=vb1.y; Bs[0][c0+2][r1]=vb1.z; Bs[0][c0+3][r1]=vb1.w;
    }
    __syncthreads();

    int nk = K / BKD;
    int buf = 0;
    for (int kt = 0; kt < nk; ++kt) {
        float4 pa0, pa1, pb0, pb1;
        bool pre = (kt + 1 < nk);
        if (pre) {
            long kb = (long)(kt + 1) * BKD;
            pa0 = *(const float4*)&A[(long)(m0 + r0) * K + kb + c0];
            pa1 = *(const float4*)&A[(long)(m0 + r1) * K + kb + c0];
            pb0 = *(const float4*)&W[(long)(n0 + r0) * K + kb + c0];
            pb1 = *(const float4*)&W[(long)(n0 + r1) * K + kb + c0];
        }
        #pragma unroll
        for (int kk = 0; kk < BKD; ++kk) {
            float4 a0 = *(const float4*)&As[buf][kk][tr * 8];
            float4 a1 = *(const float4*)&As[buf][kk][tr * 8 + 4];
            float4 b0 = *(const float4*)&Bs[buf][kk][tc * 8];
            float4 b1 = *(const float4*)&Bs[buf][kk][tc * 8 + 4];
            float a[8] = {a0.x,a0.y,a0.z,a0.w,a1.x,a1.y,a1.z,a1.w};
            float b[8] = {b0.x,b0.y,b0.z,b0.w,b1.x,b1.y,b1.z,b1.w};
            #pragma unroll
            for (int i = 0; i < 8; i++)
                #pragma unroll
                for (int j = 0; j < 8; j++)
                    acc[i][j] = fmaf(a[i], b[j], acc[i][j]);
        }
        if (pre) {
            int nb = buf ^ 1;
            As[nb][c0+0][r0]=pa0.x; As[nb][c0+1][r0]=pa0.y; As[nb][c0+2][r0]=pa0.z; As[nb][c0+3][r0]=pa0.w;
            As[nb][c0+0][r1]=pa1.x; As[nb][c0+1][r1]=pa1.y; As[nb][c0+2][r1]=pa1.z; As[nb][c0+3][r1]=pa1.w;
            Bs[nb][c0+0][r0]=pb0.x; Bs[nb][c0+1][r0]=pb0.y; Bs[nb][c0+2][r0]=pb0.z; Bs[nb][c0+3][r0]=pb0.w;
            Bs[nb][c0+0][r1]=pb1.x; Bs[nb][c0+1][r1]=pb1.y; Bs[nb][c0+2][r1]=pb1.z; Bs[nb][c0+3][r1]=pb1.w;
            __syncthreads();
            buf = nb;
        }
    }

    // epilogue
    #pragma unroll
    for (int i = 0; i < 8; i++) {
        long row = m0 + tr * 8 + i;
        #pragma unroll
        for (int jj = 0; jj < 2; jj++) {
            int col = n0 + tc * 8 + jj * 4;
            float4 v;
            float* vv = (float*)&v;
            #pragma unroll
            for (int j = 0; j < 4; j++) {
                float a = acc[i][jj * 4 + j];
                if (MODE == 2) {
                    a = gelu_f(a + bias[col + j]);
                } else if (MODE == 3) {
                    a = g_arena[resOff + row * (long)Nout + col + j] + a + bias[col + j];
                }
                vv[j] = a;
            }
            *(float4*)&Cp[row * (long)Nout + col] = v;
        }
    }
}

// ---------------- flash attention ----------------
// grid: (NSEQ/128, HNUM, STAGES*BATCH). 128 threads, one query per thread.
// K/V streamed in 32-key tiles through smem; online softmax; o accumulated in regs.
#define BQ  128
#define BKT 32

__global__ __launch_bounds__(128)
void attn_kernel()
{
    int z = blockIdx.z;
    int b = z & 7;
    int stage = z >> 3;
    int hh = blockIdx.y;
    int q0 = blockIdx.x * BQ;
    int t = threadIdx.x;

    const float* qbase = g_arena + OFF_QKV + (long)(b * NSEQ) * QKVW + stage * 2304 + hh * HDIM;

    __shared__ __align__(16) float Ks[BKT][HDIM];
    __shared__ __align__(16) float Vs[BKT][HDIM];
    __shared__ float Ss[BQ][BKT + 1];

    float q[HDIM];
    {
        const float* qp = qbase + (long)(q0 + t) * QKVW;
        #pragma unroll
        for (int d4 = 0; d4 < 16; d4++) {
            float4 v = *(const float4*)&qp[d4 * 4];
            q[d4*4+0] = v.x; q[d4*4+1] = v.y; q[d4*4+2] = v.z; q[d4*4+3] = v.w;
        }
    }

    float o_[HDIM];
    #pragma unroll
    for (int d = 0; d < HDIM; d++) o_[d] = 0.0f;
    float m = -1e30f, l = 0.0f;

    for (int k0 = 0; k0 < NSEQ; k0 += BKT) {
        __syncthreads();   // protect Ks/Vs from previous-tile readers
        // load 32x64 K and V tiles: 512 float4 each / 128 threads = 4 each
        #pragma unroll
        for (int i = 0; i < 4; i++) {
            int f = t + i * 128;           // 0..511
            int row = f >> 4;
            int c4 = (f & 15) * 4;
            const float* kp = qbase + CDIM + (long)(k0 + row) * QKVW + c4;
            *(float4*)&Ks[row][c4] = *(const float4*)kp;
            const float* vp = qbase + 2 * CDIM + (long)(k0 + row) * QKVW + c4;
            *(float4*)&Vs[row][c4] = *(const float4*)vp;
        }
        __syncthreads();

        float tmax = -1e30f;
        #pragma unroll
        for (int j = 0; j < BKT; j++) {
            float s = 0.0f;
            #pragma unroll
            for (int d4 = 0; d4 < 16; d4++) {
                float4 kv = *(const float4*)&Ks[j][d4 * 4];
                s = fmaf(q[d4*4+0], kv.x, s);
                s = fmaf(q[d4*4+1], kv.y, s);
                s = fmaf(q[d4*4+2], kv.z, s);
                s = fmaf(q[d4*4+3], kv.w, s);
            }
            s *= 0.125f;                   // HD^-0.5
            Ss[t][j] = s;
            tmax = fmaxf(tmax, s);
        }

        float mnew = fmaxf(m, tmax);
        float corr = __expf(m - mnew);
        l *= corr;
        #pragma unroll
        for (int d = 0; d < HDIM; d++) o_[d] *= corr;

        #pragma unroll
        for (int j = 0; j < BKT; j++) {
            float p = __expf(Ss[t][j] - mnew);
            l += p;
            #pragma unroll
            for (int d4 = 0; d4 < 16; d4++) {
                float4 vv = *(const float4*)&Vs[j][d4 * 4];
                o_[d4*4+0] = fmaf(p, vv.x, o_[d4*4+0]);
                o_[d4*4+1] = fmaf(p, vv.y, o_[d4*4+1]);
                o_[d4*4+2] = fmaf(p, vv.z, o_[d4*4+2]);
                o_[d4*4+3] = fmaf(p, vv.w, o_[d4*4+3]);
            }
        }
        m = mnew;
    }

    float inv = 1.0f / l;
    float* op = g_arena + OFF_O + ((long)stage * TOK + (long)b * NSEQ + q0 + t) * CDIM + hh * HDIM;
    #pragma unroll
    for (int d4 = 0; d4 < 16; d4++) {
        float4 v;
        v.x = o_[d4*4+0] * inv; v.y = o_[d4*4+1] * inv;
        v.z = o_[d4*4+2] * inv; v.w = o_[d4*4+3] * inv;
        *(float4*)&op[d4 * 4] = v;
    }
}

// ---------------- combine: x1 = x + sum_i fw[i]*(p_i + proj_b_i) ----------------
__global__ void combine_kernel(const float* __restrict__ x, const float* __restrict__ pb,
                               const float* __restrict__ fw)
{
    long idx = (long)blockIdx.x * 256 + threadIdx.x;
    int c = (int)(idx % CDIM);
    const float* p = g_arena + OFF_P;
    float f0 = __ldg(&fw[0]), f1 = __ldg(&fw[1]), f2 = __ldg(&fw[2]);
    float v = x[idx];
    v = fmaf(f0, p[idx]           + pb[c],            v);
    v = fmaf(f1, p[TOKC + idx]    + pb[CDIM + c],     v);
    v = fmaf(f2, p[2*TOKC + idx]  + pb[2*CDIM + c],   v);
    g_arena[OFF_X1 + idx] = v;
}

// ---------------- launch ----------------
extern "C" void kernel_launch(void* const* d_in, const int* in_sizes, int n_in,
                              void* d_out, int out_size)
{
    const float* x      = (const float*)d_in[0];
    const float* qkv_w  = (const float*)d_in[1];   // [3, 2304, 768] contiguous -> [6912, 768]
    const float* proj_w = (const float*)d_in[2];   // [3, 768, 768]
    const float* proj_b = (const float*)d_in[3];   // [3, 768]
    const float* ln1_w  = (const float*)d_in[4];
    const float* ln1_b  = (const float*)d_in[5];
    const float* ln2_w  = (const float*)d_in[6];
    const float* ln2_b  = (const float*)d_in[7];
    const float* mlp_w1 = (const float*)d_in[8];   // [3072, 768]
    const float* mlp_b1 = (const float*)d_in[9];
    const float* mlp_w2 = (const float*)d_in[10];  // [768, 3072]
    const float* mlp_b2 = (const float*)d_in[11];
    const float* fw     = (const float*)d_in[12];  // [3]
    float* out = (float*)d_out;

    // 1) h = LN1(x)
    ln_kernel<<<TOK, 256>>>(x, 0, ln1_w, ln1_b, OFF_H);

    // 2) qkv(all stages) = h @ qkv_w_all^T   [8192 x 6912]
    sgemm<0><<<dim3(QKVW / BN, TOK / BM, 1), 256>>>(
        OFF_H, qkv_w, OFF_QKV, nullptr, nullptr, 0,
        TOK, QKVW, CDIM, 0, 0, 0);

    // 3) attention, all stages
    attn_kernel<<<dim3(NSEQ / BQ, HNUM, STAGES * BATCH), 128>>>();

    // 4) p_i = o_i @ proj_w_i^T   (batched over stage)
    sgemm<0><<<dim3(CDIM / BN, TOK / BM, STAGES), 256>>>(
        OFF_O, proj_w, OFF_P, nullptr, nullptr, 0,
        TOK, CDIM, CDIM, TOKC, (long)CDIM * CDIM, TOKC);

    // 5) x1 = x + sum_i fw[i]*(p_i + proj_b_i)
    combine_kernel<<<(int)(TOKC / 256), 256>>>(x, proj_b, fw);

    // 6) h2 = LN2(x1)
    ln_kernel<<<TOK, 256>>>(nullptr, OFF_X1, ln2_w, ln2_b, OFF_H2);

    // 7) g = gelu(h2 @ mlp_w1^T + b1)   [8192 x 3072]
    sgemm<2><<<dim3(MLPH / BN, TOK / BM, 1), 256>>>(
        OFF_H2, mlp_w1, OFF_G, nullptr, mlp_b1, 0,
        TOK, MLPH, CDIM, 0, 0, 0);

    // 8) out = x1 + g @ mlp_w2^T + b2
    sgemm<3><<<dim3(CDIM / BN, TOK / BM, 1), 256>>>(
        OFF_G, mlp_w2, 0, out, mlp_b2, OFF_X1,
        TOK, CDIM, MLPH, 0, 0, 0);
}

// round 5
// speedup vs baseline: 1.2826x; 1.2826x over previous
#include <cuda_runtime.h>
#include <math.h>
#include <stdint.h>

// ---------------- problem constants ----------------
#define TOK    8192        // B*N
#define CDIM   768
#define HNUM   12
#define HDIM   64
#define NSEQ   1024
#define BATCH  8
#define MLPH   3072
#define QKVW   6912        // 3 stages * 3*C
#define STAGES 3

constexpr long TOKC   = (long)TOK * CDIM;
constexpr long OFF_H   = 0;
constexpr long OFF_QKV = OFF_H   + TOKC;
constexpr long OFF_O   = OFF_QKV + (long)TOK*QKVW;
constexpr long OFF_P   = OFF_O   + 3*TOKC;
constexpr long OFF_X1  = OFF_P   + 3*TOKC;
constexpr long OFF_H2  = OFF_X1  + TOKC;
constexpr long OFF_G   = OFF_H2  + TOKC;
constexpr long ARENA_SZ = OFF_G  + (long)TOK*MLPH;

__device__ float g_arena[ARENA_SZ];

// ---------------- helpers ----------------
__device__ __forceinline__ uint32_t f2tf32(float f) {
    uint32_t o;
    asm("cvt.rna.tf32.f32 %0, %1;" : "=r"(o) : "f"(f));
    return o;
}

__device__ __forceinline__ void mma_tf32(float* c, const uint32_t* a, const uint32_t* b) {
    asm volatile(
        "mma.sync.aligned.m16n8k8.row.col.f32.tf32.tf32.f32 "
        "{%0,%1,%2,%3}, {%4,%5,%6,%7}, {%8,%9}, {%0,%1,%2,%3};\n"
        : "+f"(c[0]), "+f"(c[1]), "+f"(c[2]), "+f"(c[3])
        : "r"(a[0]), "r"(a[1]), "r"(a[2]), "r"(a[3]), "r"(b[0]), "r"(b[1]));
}

__device__ __forceinline__ float gelu_f(float v) {
    return 0.5f * v * (1.0f + erff(v * 0.70710678118654752440f));
}

// ---------------- layernorm ----------------
__global__ void ln_kernel(const float* __restrict__ xext, long xOff,
                          const float* __restrict__ w, const float* __restrict__ b,
                          long outOff)
{
    int row = blockIdx.x;
    const float* xr = (xext ? xext : (const float*)(g_arena + xOff)) + (long)row * CDIM;
    int t = threadIdx.x;
    float v0 = xr[t], v1 = xr[t + 256], v2 = xr[t + 512];
    float s = v0 + v1 + v2;

    __shared__ float red[8];
    #pragma unroll
    for (int o = 16; o > 0; o >>= 1) s += __shfl_xor_sync(0xffffffffu, s, o);
    if ((t & 31) == 0) red[t >> 5] = s;
    __syncthreads();
    float tot = red[0]+red[1]+red[2]+red[3]+red[4]+red[5]+red[6]+red[7];
    float mu = tot * (1.0f / CDIM);

    float d0 = v0 - mu, d1 = v1 - mu, d2 = v2 - mu;
    float q = d0*d0 + d1*d1 + d2*d2;
    #pragma unroll
    for (int o = 16; o > 0; o >>= 1) q += __shfl_xor_sync(0xffffffffu, q, o);
    __syncthreads();
    if ((t & 31) == 0) red[t >> 5] = q;
    __syncthreads();
    float qt = red[0]+red[1]+red[2]+red[3]+red[4]+red[5]+red[6]+red[7];
    float inv = rsqrtf(qt * (1.0f / CDIM) + 1e-5f);

    float* op = g_arena + outOff + (long)row * CDIM;
    op[t      ] = d0 * inv * w[t      ] + b[t      ];
    op[t + 256] = d1 * inv * w[t + 256] + b[t + 256];
    op[t + 512] = d2 * inv * w[t + 512] + b[t + 512];
}

// ---------------- TF32 mma.sync GEMM: C[m,n] = sum_k A[m,k]*W[n,k] ----------------
// 128x128 tile, BK=16, 256 threads (8 warps, 2x4 warp grid, 64x32 warp tile).
// k-major smem [16][136] (tf32 bits), register-prefetch double buffering.
// MODE 0: C = acc;  MODE 2: C = gelu(acc+bias);  MODE 3: C = res + acc + bias (into Cext)
#define SPAD 136

template<int MODE>
__global__ __launch_bounds__(256)
void mma_gemm(long aOff, const float* __restrict__ Wt, long cOff, float* __restrict__ Cext,
              const float* __restrict__ bias, long resOff,
              int K, int Nout, long aStride, long wStride, long cStride)
{
    const float* A = g_arena + aOff + (long)blockIdx.z * aStride;
    const float* W = Wt + (long)blockIdx.z * wStride;
    float* Cp = Cext ? Cext : (g_arena + cOff + (long)blockIdx.z * cStride);

    int m0 = blockIdx.y * 128;
    int n0 = blockIdx.x * 128;
    int tid = threadIdx.x, lane = tid & 31, wid = tid >> 5;
    int wm = (wid & 1) * 64;          // warp m offset in tile
    int wn = (wid >> 1) * 32;         // warp n offset in tile
    int g = lane >> 2, tg = lane & 3;

    __shared__ uint32_t As[2][16][SPAD];
    __shared__ uint32_t Bs[2][16][SPAD];

    float c[4][4][4] = {};            // [mt][nt][reg]

    // load mapping: row = tid&127, k-quads q0 and q0+8 (q0 = (tid>>7)*4)
    int lrow = tid & 127;
    int q0 = (tid >> 7) * 4;

    const float* arow = &A[(long)(m0 + lrow) * K + q0];
    const float* brow = &W[(long)(n0 + lrow) * K + q0];

    // tile 0 -> smem
    {
        float4 a0 = *(const float4*)arow;
        float4 a1 = *(const float4*)(arow + 8);
        float4 b0 = *(const float4*)brow;
        float4 b1 = *(const float4*)(brow + 8);
        const float* af = (const float*)&a0;
        const float* ag = (const float*)&a1;
        const float* bf = (const float*)&b0;
        const float* bg = (const float*)&b1;
        #pragma unroll
        for (int j = 0; j < 4; j++) {
            As[0][q0 + j][lrow]     = f2tf32(af[j]);
            As[0][q0 + 8 + j][lrow] = f2tf32(ag[j]);
            Bs[0][q0 + j][lrow]     = f2tf32(bf[j]);
            Bs[0][q0 + 8 + j][lrow] = f2tf32(bg[j]);
        }
    }
    __syncthreads();

    int nk = K >> 4;
    int buf = 0;
    for (int kt = 0; kt < nk; ++kt) {
        float4 pa0, pa1, pb0, pb1;
        bool pre = (kt + 1 < nk);
        if (pre) {
            const float* an = arow + (kt + 1) * 16;
            const float* bn = brow + (kt + 1) * 16;
            pa0 = *(const float4*)an;
            pa1 = *(const float4*)(an + 8);
            pb0 = *(const float4*)bn;
            pb1 = *(const float4*)(bn + 8);
        }

        #pragma unroll
        for (int ks = 0; ks < 2; ks++) {
            int kb = ks * 8;
            uint32_t af[4][4];
            #pragma unroll
            for (int mt = 0; mt < 4; mt++) {
                int mcol = wm + mt * 16 + g;
                af[mt][0] = As[buf][kb + tg][mcol];
                af[mt][1] = As[buf][kb + tg][mcol + 8];
                af[mt][2] = As[buf][kb + tg + 4][mcol];
                af[mt][3] = As[buf][kb + tg + 4][mcol + 8];
            }
            uint32_t bfr[4][2];
            #pragma unroll
            for (int nt = 0; nt < 4; nt++) {
                int ncol = wn + nt * 8 + g;
                bfr[nt][0] = Bs[buf][kb + tg][ncol];
                bfr[nt][1] = Bs[buf][kb + tg + 4][ncol];
            }
            #pragma unroll
            for (int mt = 0; mt < 4; mt++)
                #pragma unroll
                for (int nt = 0; nt < 4; nt++)
                    mma_tf32(c[mt][nt], af[mt], bfr[nt]);
        }

        if (pre) {
            int nb = buf ^ 1;
            const float* af = (const float*)&pa0;
            const float* ag = (const float*)&pa1;
            const float* bf = (const float*)&pb0;
            const float* bg = (const float*)&pb1;
            #pragma unroll
            for (int j = 0; j < 4; j++) {
                As[nb][q0 + j][lrow]     = f2tf32(af[j]);
                As[nb][q0 + 8 + j][lrow] = f2tf32(ag[j]);
                Bs[nb][q0 + j][lrow]     = f2tf32(bf[j]);
                Bs[nb][q0 + 8 + j][lrow] = f2tf32(bg[j]);
            }
            __syncthreads();
            buf = nb;
        }
    }

    // epilogue: c[mt][nt]: rows m0+wm+mt*16+g(+8), cols n0+wn+nt*8+tg*2(+1)
    #pragma unroll
    for (int mt = 0; mt < 4; mt++) {
        #pragma unroll
        for (int half = 0; half < 2; half++) {
            long row = m0 + wm + mt * 16 + g + half * 8;
            #pragma unroll
            for (int nt = 0; nt < 4; nt++) {
                int col = n0 + wn + nt * 8 + tg * 2;
                float v0 = c[mt][nt][half * 2 + 0];
                float v1 = c[mt][nt][half * 2 + 1];
                if (MODE == 2) {
                    v0 = gelu_f(v0 + bias[col]);
                    v1 = gelu_f(v1 + bias[col + 1]);
                } else if (MODE == 3) {
                    float2 r = *(const float2*)&g_arena[resOff + row * (long)Nout + col];
                    v0 = r.x + v0 + bias[col];
                    v1 = r.y + v1 + bias[col + 1];
                }
                float2 o; o.x = v0; o.y = v1;
                *(float2*)&Cp[row * (long)Nout + col] = o;
            }
        }
    }
}

// ---------------- flash attention (SIMT, unchanged from R1) ----------------
#define BQ  128
#define BKT 32

__global__ __launch_bounds__(128)
void attn_kernel()
{
    int z = blockIdx.z;
    int b = z & 7;
    int stage = z >> 3;
    int hh = blockIdx.y;
    int q0 = blockIdx.x * BQ;
    int t = threadIdx.x;

    const float* qbase = g_arena + OFF_QKV + (long)(b * NSEQ) * QKVW + stage * 2304 + hh * HDIM;

    __shared__ __align__(16) float Ks[BKT][HDIM];
    __shared__ __align__(16) float Vs[BKT][HDIM];
    __shared__ float Ss[BQ][BKT + 1];

    float q[HDIM];
    {
        const float* qp = qbase + (long)(q0 + t) * QKVW;
        #pragma unroll
        for (int d4 = 0; d4 < 16; d4++) {
            float4 v = *(const float4*)&qp[d4 * 4];
            q[d4*4+0] = v.x; q[d4*4+1] = v.y; q[d4*4+2] = v.z; q[d4*4+3] = v.w;
        }
    }

    float o_[HDIM];
    #pragma unroll
    for (int d = 0; d < HDIM; d++) o_[d] = 0.0f;
    float m = -1e30f, l = 0.0f;

    for (int k0 = 0; k0 < NSEQ; k0 += BKT) {
        __syncthreads();
        #pragma unroll
        for (int i = 0; i < 4; i++) {
            int f = t + i * 128;
            int row = f >> 4;
            int c4 = (f & 15) * 4;
            const float* kp = qbase + CDIM + (long)(k0 + row) * QKVW + c4;
            *(float4*)&Ks[row][c4] = *(const float4*)kp;
            const float* vp = qbase + 2 * CDIM + (long)(k0 + row) * QKVW + c4;
            *(float4*)&Vs[row][c4] = *(const float4*)vp;
        }
        __syncthreads();

        float tmax = -1e30f;
        #pragma unroll
        for (int j = 0; j < BKT; j++) {
            float s = 0.0f;
            #pragma unroll
            for (int d4 = 0; d4 < 16; d4++) {
                float4 kv = *(const float4*)&Ks[j][d4 * 4];
                s = fmaf(q[d4*4+0], kv.x, s);
                s = fmaf(q[d4*4+1], kv.y, s);
                s = fmaf(q[d4*4+2], kv.z, s);
                s = fmaf(q[d4*4+3], kv.w, s);
            }
            s *= 0.125f;
            Ss[t][j] = s;
            tmax = fmaxf(tmax, s);
        }

        float mnew = fmaxf(m, tmax);
        float corr = __expf(m - mnew);
        l *= corr;
        #pragma unroll
        for (int d = 0; d < HDIM; d++) o_[d] *= corr;

        #pragma unroll
        for (int j = 0; j < BKT; j++) {
            float p = __expf(Ss[t][j] - mnew);
            l += p;
            #pragma unroll
            for (int d4 = 0; d4 < 16; d4++) {
                float4 vv = *(const float4*)&Vs[j][d4 * 4];
                o_[d4*4+0] = fmaf(p, vv.x, o_[d4*4+0]);
                o_[d4*4+1] = fmaf(p, vv.y, o_[d4*4+1]);
                o_[d4*4+2] = fmaf(p, vv.z, o_[d4*4+2]);
                o_[d4*4+3] = fmaf(p, vv.w, o_[d4*4+3]);
            }
        }
        m = mnew;
    }

    float inv = 1.0f / l;
    float* op = g_arena + OFF_O + ((long)stage * TOK + (long)b * NSEQ + q0 + t) * CDIM + hh * HDIM;
    #pragma unroll
    for (int d4 = 0; d4 < 16; d4++) {
        float4 v;
        v.x = o_[d4*4+0] * inv; v.y = o_[d4*4+1] * inv;
        v.z = o_[d4*4+2] * inv; v.w = o_[d4*4+3] * inv;
        *(float4*)&op[d4 * 4] = v;
    }
}

// ---------------- combine: x1 = x + sum_i fw[i]*(p_i + proj_b_i) ----------------
__global__ void combine_kernel(const float* __restrict__ x, const float* __restrict__ pb,
                               const float* __restrict__ fw)
{
    long idx = (long)blockIdx.x * 256 + threadIdx.x;
    int c = (int)(idx % CDIM);
    const float* p = g_arena + OFF_P;
    float f0 = __ldg(&fw[0]), f1 = __ldg(&fw[1]), f2 = __ldg(&fw[2]);
    float v = x[idx];
    v = fmaf(f0, p[idx]           + pb[c],            v);
    v = fmaf(f1, p[TOKC + idx]    + pb[CDIM + c],     v);
    v = fmaf(f2, p[2*TOKC + idx]  + pb[2*CDIM + c],   v);
    g_arena[OFF_X1 + idx] = v;
}

// ---------------- launch ----------------
extern "C" void kernel_launch(void* const* d_in, const int* in_sizes, int n_in,
                              void* d_out, int out_size)
{
    const float* x      = (const float*)d_in[0];
    const float* qkv_w  = (const float*)d_in[1];
    const float* proj_w = (const float*)d_in[2];
    const float* proj_b = (const float*)d_in[3];
    const float* ln1_w  = (const float*)d_in[4];
    const float* ln1_b  = (const float*)d_in[5];
    const float* ln2_w  = (const float*)d_in[6];
    const float* ln2_b  = (const float*)d_in[7];
    const float* mlp_w1 = (const float*)d_in[8];
    const float* mlp_b1 = (const float*)d_in[9];
    const float* mlp_w2 = (const float*)d_in[10];
    const float* mlp_b2 = (const float*)d_in[11];
    const float* fw     = (const float*)d_in[12];
    float* out = (float*)d_out;

    // 1) h = LN1(x)
    ln_kernel<<<TOK, 256>>>(x, 0, ln1_w, ln1_b, OFF_H);

    // 2) qkv(all stages) = h @ qkv_w_all^T   [8192 x 6912]
    mma_gemm<0><<<dim3(QKVW / 128, TOK / 128, 1), 256>>>(
        OFF_H, qkv_w, OFF_QKV, nullptr, nullptr, 0, CDIM, QKVW, 0, 0, 0);

    // 3) attention, all stages
    attn_kernel<<<dim3(NSEQ / BQ, HNUM, STAGES * BATCH), 128>>>();

    // 4) p_i = o_i @ proj_w_i^T (batched over stage)
    mma_gemm<0><<<dim3(CDIM / 128, TOK / 128, STAGES), 256>>>(
        OFF_O, proj_w, OFF_P, nullptr, nullptr, 0, CDIM, CDIM,
        TOKC, (long)CDIM * CDIM, TOKC);

    // 5) x1 = x + sum_i fw[i]*(p_i + proj_b_i)
    combine_kernel<<<(int)(TOKC / 256), 256>>>(x, proj_b, fw);

    // 6) h2 = LN2(x1)
    ln_kernel<<<TOK, 256>>>(nullptr, OFF_X1, ln2_w, ln2_b, OFF_H2);

    // 7) g = gelu(h2 @ mlp_w1^T + b1)   [8192 x 3072]
    mma_gemm<2><<<dim3(MLPH / 128, TOK / 128, 1), 256>>>(
        OFF_H2, mlp_w1, OFF_G, nullptr, mlp_b1, 0, CDIM, MLPH, 0, 0, 0);

    // 8) out = x1 + g @ mlp_w2^T + b2
    mma_gemm<3><<<dim3(CDIM / 128, TOK / 128, 1), 256>>>(
        OFF_G, mlp_w2, 0, out, mlp_b2, OFF_X1, MLPH, CDIM, 0, 0, 0);
}

// round 6
// speedup vs baseline: 1.9477x; 1.5186x over previous
#include <cuda_runtime.h>
#include <math.h>
#include <stdint.h>

// ---------------- problem constants ----------------
#define TOK    8192        // B*N
#define CDIM   768
#define HNUM   12
#define HDIM   64
#define NSEQ   1024
#define BATCH  8
#define MLPH   3072
#define QKVW   6912        // 3 stages * 3*C
#define STAGES 3

constexpr long TOKC   = (long)TOK * CDIM;
constexpr long OFF_H   = 0;
constexpr long OFF_QKV = OFF_H   + TOKC;
constexpr long OFF_O   = OFF_QKV + (long)TOK*QKVW;
constexpr long OFF_P   = OFF_O   + 3*TOKC;
constexpr long OFF_X1  = OFF_P   + 3*TOKC;
constexpr long OFF_H2  = OFF_X1  + TOKC;
constexpr long OFF_G   = OFF_H2  + TOKC;
constexpr long ARENA_SZ = OFF_G  + (long)TOK*MLPH;

__device__ float g_arena[ARENA_SZ];

// ---------------- helpers ----------------
__device__ __forceinline__ uint32_t f2tf32(float f) {
    uint32_t o;
    asm("cvt.rna.tf32.f32 %0, %1;" : "=r"(o) : "f"(f));
    return o;
}

__device__ __forceinline__ void mma_tf32(float* c, const uint32_t* a, const uint32_t* b) {
    asm volatile(
        "mma.sync.aligned.m16n8k8.row.col.f32.tf32.tf32.f32 "
        "{%0,%1,%2,%3}, {%4,%5,%6,%7}, {%8,%9}, {%0,%1,%2,%3};\n"
        : "+f"(c[0]), "+f"(c[1]), "+f"(c[2]), "+f"(c[3])
        : "r"(a[0]), "r"(a[1]), "r"(a[2]), "r"(a[3]), "r"(b[0]), "r"(b[1]));
}

__device__ __forceinline__ float gelu_f(float v) {
    return 0.5f * v * (1.0f + erff(v * 0.70710678118654752440f));
}

// ---------------- layernorm ----------------
__global__ void ln_kernel(const float* __restrict__ xext, long xOff,
                          const float* __restrict__ w, const float* __restrict__ b,
                          long outOff)
{
    int row = blockIdx.x;
    const float* xr = (xext ? xext : (const float*)(g_arena + xOff)) + (long)row * CDIM;
    int t = threadIdx.x;
    float v0 = xr[t], v1 = xr[t + 256], v2 = xr[t + 512];
    float s = v0 + v1 + v2;

    __shared__ float red[8];
    #pragma unroll
    for (int o = 16; o > 0; o >>= 1) s += __shfl_xor_sync(0xffffffffu, s, o);
    if ((t & 31) == 0) red[t >> 5] = s;
    __syncthreads();
    float tot = red[0]+red[1]+red[2]+red[3]+red[4]+red[5]+red[6]+red[7];
    float mu = tot * (1.0f / CDIM);

    float d0 = v0 - mu, d1 = v1 - mu, d2 = v2 - mu;
    float q = d0*d0 + d1*d1 + d2*d2;
    #pragma unroll
    for (int o = 16; o > 0; o >>= 1) q += __shfl_xor_sync(0xffffffffu, q, o);
    __syncthreads();
    if ((t & 31) == 0) red[t >> 5] = q;
    __syncthreads();
    float qt = red[0]+red[1]+red[2]+red[3]+red[4]+red[5]+red[6]+red[7];
    float inv = rsqrtf(qt * (1.0f / CDIM) + 1e-5f);

    float* op = g_arena + outOff + (long)row * CDIM;
    op[t      ] = d0 * inv * w[t      ] + b[t      ];
    op[t + 256] = d1 * inv * w[t + 256] + b[t + 256];
    op[t + 512] = d2 * inv * w[t + 512] + b[t + 512];
}

// ---------------- TF32 mma.sync GEMM (unchanged from R5 passing version) ----------------
#define SPAD 136

template<int MODE>
__global__ __launch_bounds__(256)
void mma_gemm(long aOff, const float* __restrict__ Wt, long cOff, float* __restrict__ Cext,
              const float* __restrict__ bias, long resOff,
              int K, int Nout, long aStride, long wStride, long cStride)
{
    const float* A = g_arena + aOff + (long)blockIdx.z * aStride;
    const float* W = Wt + (long)blockIdx.z * wStride;
    float* Cp = Cext ? Cext : (g_arena + cOff + (long)blockIdx.z * cStride);

    int m0 = blockIdx.y * 128;
    int n0 = blockIdx.x * 128;
    int tid = threadIdx.x, lane = tid & 31, wid = tid >> 5;
    int wm = (wid & 1) * 64;
    int wn = (wid >> 1) * 32;
    int g = lane >> 2, tg = lane & 3;

    __shared__ uint32_t As[2][16][SPAD];
    __shared__ uint32_t Bs[2][16][SPAD];

    float c[4][4][4] = {};

    int lrow = tid & 127;
    int q0 = (tid >> 7) * 4;

    const float* arow = &A[(long)(m0 + lrow) * K + q0];
    const float* brow = &W[(long)(n0 + lrow) * K + q0];

    {
        float4 a0 = *(const float4*)arow;
        float4 a1 = *(const float4*)(arow + 8);
        float4 b0 = *(const float4*)brow;
        float4 b1 = *(const float4*)(brow + 8);
        const float* af = (const float*)&a0;
        const float* ag = (const float*)&a1;
        const float* bf = (const float*)&b0;
        const float* bg = (const float*)&b1;
        #pragma unroll
        for (int j = 0; j < 4; j++) {
            As[0][q0 + j][lrow]     = f2tf32(af[j]);
            As[0][q0 + 8 + j][lrow] = f2tf32(ag[j]);
            Bs[0][q0 + j][lrow]     = f2tf32(bf[j]);
            Bs[0][q0 + 8 + j][lrow] = f2tf32(bg[j]);
        }
    }
    __syncthreads();

    int nk = K >> 4;
    int buf = 0;
    for (int kt = 0; kt < nk; ++kt) {
        float4 pa0, pa1, pb0, pb1;
        bool pre = (kt + 1 < nk);
        if (pre) {
            const float* an = arow + (kt + 1) * 16;
            const float* bn = brow + (kt + 1) * 16;
            pa0 = *(const float4*)an;
            pa1 = *(const float4*)(an + 8);
            pb0 = *(const float4*)bn;
            pb1 = *(const float4*)(bn + 8);
        }

        #pragma unroll
        for (int ks = 0; ks < 2; ks++) {
            int kb = ks * 8;
            uint32_t af[4][4];
            #pragma unroll
            for (int mt = 0; mt < 4; mt++) {
                int mcol = wm + mt * 16 + g;
                af[mt][0] = As[buf][kb + tg][mcol];
                af[mt][1] = As[buf][kb + tg][mcol + 8];
                af[mt][2] = As[buf][kb + tg + 4][mcol];
                af[mt][3] = As[buf][kb + tg + 4][mcol + 8];
            }
            uint32_t bfr[4][2];
            #pragma unroll
            for (int nt = 0; nt < 4; nt++) {
                int ncol = wn + nt * 8 + g;
                bfr[nt][0] = Bs[buf][kb + tg][ncol];
                bfr[nt][1] = Bs[buf][kb + tg + 4][ncol];
            }
            #pragma unroll
            for (int mt = 0; mt < 4; mt++)
                #pragma unroll
                for (int nt = 0; nt < 4; nt++)
                    mma_tf32(c[mt][nt], af[mt], bfr[nt]);
        }

        if (pre) {
            int nb = buf ^ 1;
            const float* af = (const float*)&pa0;
            const float* ag = (const float*)&pa1;
            const float* bf = (const float*)&pb0;
            const float* bg = (const float*)&pb1;
            #pragma unroll
            for (int j = 0; j < 4; j++) {
                As[nb][q0 + j][lrow]     = f2tf32(af[j]);
                As[nb][q0 + 8 + j][lrow] = f2tf32(ag[j]);
                Bs[nb][q0 + j][lrow]     = f2tf32(bf[j]);
                Bs[nb][q0 + 8 + j][lrow] = f2tf32(bg[j]);
            }
            __syncthreads();
            buf = nb;
        }
    }

    #pragma unroll
    for (int mt = 0; mt < 4; mt++) {
        #pragma unroll
        for (int half = 0; half < 2; half++) {
            long row = m0 + wm + mt * 16 + g + half * 8;
            #pragma unroll
            for (int nt = 0; nt < 4; nt++) {
                int col = n0 + wn + nt * 8 + tg * 2;
                float v0 = c[mt][nt][half * 2 + 0];
                float v1 = c[mt][nt][half * 2 + 1];
                if (MODE == 2) {
                    v0 = gelu_f(v0 + bias[col]);
                    v1 = gelu_f(v1 + bias[col + 1]);
                } else if (MODE == 3) {
                    float2 r = *(const float2*)&g_arena[resOff + row * (long)Nout + col];
                    v0 = r.x + v0 + bias[col];
                    v1 = r.y + v1 + bias[col + 1];
                }
                float2 o; o.x = v0; o.y = v1;
                *(float2*)&Cp[row * (long)Nout + col] = o;
            }
        }
    }
}

// ---------------- tensor-core flash attention ----------------
// CTA: 128 q rows, 4 warps x 32 rows. 32-key tiles. tf32 mma for QK^T and PV.
// Fragment conventions identical to mma_gemm (validated): A row-major m16k8,
// B as n-major [n][k], C: c0=(g,2tg) c1=(g,2tg+1) c2=(g+8,2tg) c3=(g+8,2tg+1).
#define ATK 32

__global__ __launch_bounds__(128)
void attn_mma_kernel()
{
    int z = blockIdx.z;
    int b = z & 7;
    int stage = z >> 3;
    int hh = blockIdx.y;
    int q0 = blockIdx.x * 128;
    int tid = threadIdx.x;
    int warp = tid >> 5, lane = tid & 31;
    int g = lane >> 2, tg = lane & 3;

    const float* qbase = g_arena + OFF_QKV + (long)(b * NSEQ) * QKVW + stage * 2304 + hh * HDIM;
    const float* kbase = qbase + CDIM;
    const float* vbase = qbase + 2 * CDIM;

    __shared__ uint32_t Ks[ATK][68];      // stride 68: b-frag banks g*4+tg distinct
    __shared__ uint32_t Vs[ATK][72];      // stride 72: b-frag banks tg*8+g distinct
    __shared__ uint32_t Ps[4][32][36];    // per-warp P; stride 36: a-frag banks g*4+tg

    // Q fragments in registers, softmax scale (1/8, exact) folded in.
    uint32_t qa[2][8][4];
    int mrow = q0 + warp * 32;
    #pragma unroll
    for (int mt = 0; mt < 2; mt++) {
        #pragma unroll
        for (int ks = 0; ks < 8; ks++) {
            const float* r0 = qbase + (long)(mrow + mt * 16 + g) * QKVW + ks * 8 + tg;
            const float* r1 = r0 + 8 * QKVW;
            qa[mt][ks][0] = f2tf32(0.125f * __ldg(r0));
            qa[mt][ks][1] = f2tf32(0.125f * __ldg(r1));
            qa[mt][ks][2] = f2tf32(0.125f * __ldg(r0 + 4));
            qa[mt][ks][3] = f2tf32(0.125f * __ldg(r1 + 4));
        }
    }

    float o[2][8][4] = {};
    float mr[4] = {-1e30f, -1e30f, -1e30f, -1e30f};
    float lr[4] = {0.f, 0.f, 0.f, 0.f};

    for (int k0 = 0; k0 < NSEQ; k0 += ATK) {
        __syncthreads();   // protect Ks/Vs from previous tile's readers
        {
            int row = tid & 31, cs = tid >> 5;       // 32 rows x 4 col-segments of 16
            const float* kp = kbase + (long)(k0 + row) * QKVW + cs * 16;
            const float* vp = vbase + (long)(k0 + row) * QKVW + cs * 16;
            #pragma unroll
            for (int j = 0; j < 4; j++) {
                float4 kv = *(const float4*)(kp + j * 4);
                float4 vv = *(const float4*)(vp + j * 4);
                int cb = cs * 16 + j * 4;
                Ks[row][cb+0] = f2tf32(kv.x); Ks[row][cb+1] = f2tf32(kv.y);
                Ks[row][cb+2] = f2tf32(kv.z); Ks[row][cb+3] = f2tf32(kv.w);
                Vs[row][cb+0] = f2tf32(vv.x); Vs[row][cb+1] = f2tf32(vv.y);
                Vs[row][cb+2] = f2tf32(vv.z); Vs[row][cb+3] = f2tf32(vv.w);
            }
        }
        __syncthreads();

        // S = Qscaled . K^T : c[mt][nt][4], keys nt*8.., 32 keys
        float c[2][4][4] = {};
        #pragma unroll
        for (int ks = 0; ks < 8; ks++) {
            uint32_t kb_[4][2];
            #pragma unroll
            for (int nt = 0; nt < 4; nt++) {
                kb_[nt][0] = Ks[nt * 8 + g][ks * 8 + tg];
                kb_[nt][1] = Ks[nt * 8 + g][ks * 8 + tg + 4];
            }
            #pragma unroll
            for (int mt = 0; mt < 2; mt++)
                #pragma unroll
                for (int nt = 0; nt < 4; nt++)
                    mma_tf32(c[mt][nt], qa[mt][ks], kb_[nt]);
        }

        // online softmax: per-thread rows: idx = mt*2 + (r>>1) -> row mt*16+g(+8)
        float tm[4] = {-1e30f, -1e30f, -1e30f, -1e30f};
        #pragma unroll
        for (int mt = 0; mt < 2; mt++)
            #pragma unroll
            for (int nt = 0; nt < 4; nt++)
                #pragma unroll
                for (int r = 0; r < 4; r++)
                    tm[mt * 2 + (r >> 1)] = fmaxf(tm[mt * 2 + (r >> 1)], c[mt][nt][r]);
        #pragma unroll
        for (int i = 0; i < 4; i++) {
            tm[i] = fmaxf(tm[i], __shfl_xor_sync(0xffffffffu, tm[i], 1));
            tm[i] = fmaxf(tm[i], __shfl_xor_sync(0xffffffffu, tm[i], 2));
        }
        float mn[4], corr[4];
        #pragma unroll
        for (int i = 0; i < 4; i++) {
            mn[i] = fmaxf(mr[i], tm[i]);
            corr[i] = __expf(mr[i] - mn[i]);
        }
        float ts[4] = {0.f, 0.f, 0.f, 0.f};
        #pragma unroll
        for (int mt = 0; mt < 2; mt++)
            #pragma unroll
            for (int nt = 0; nt < 4; nt++)
                #pragma unroll
                for (int r = 0; r < 4; r++) {
                    int i = mt * 2 + (r >> 1);
                    float p = __expf(c[mt][nt][r] - mn[i]);
                    c[mt][nt][r] = p;
                    ts[i] += p;
                }
        #pragma unroll
        for (int i = 0; i < 4; i++) {
            ts[i] += __shfl_xor_sync(0xffffffffu, ts[i], 1);
            ts[i] += __shfl_xor_sync(0xffffffffu, ts[i], 2);
            lr[i] = lr[i] * corr[i] + ts[i];
            mr[i] = mn[i];
        }
        #pragma unroll
        for (int mt = 0; mt < 2; mt++)
            #pragma unroll
            for (int nd = 0; nd < 8; nd++)
                #pragma unroll
                for (int r = 0; r < 4; r++)
                    o[mt][nd][r] *= corr[mt * 2 + (r >> 1)];

        // P -> per-warp smem (tf32), C-layout cols 2tg,2tg+1 contiguous
        #pragma unroll
        for (int mt = 0; mt < 2; mt++)
            #pragma unroll
            for (int nt = 0; nt < 4; nt++) {
                int r0 = mt * 16 + g, col = nt * 8 + tg * 2;
                uint2 p0, p1;
                p0.x = f2tf32(c[mt][nt][0]); p0.y = f2tf32(c[mt][nt][1]);
                p1.x = f2tf32(c[mt][nt][2]); p1.y = f2tf32(c[mt][nt][3]);
                *(uint2*)&Ps[warp][r0][col]     = p0;
                *(uint2*)&Ps[warp][r0 + 8][col] = p1;
            }
        __syncwarp();

        // O += P . V : k = keys (4 steps of 8), n = d (8 frags)
        #pragma unroll
        for (int kk = 0; kk < 4; kk++) {
            uint32_t pa[2][4];
            #pragma unroll
            for (int mt = 0; mt < 2; mt++) {
                pa[mt][0] = Ps[warp][mt * 16 + g]    [kk * 8 + tg];
                pa[mt][1] = Ps[warp][mt * 16 + 8 + g][kk * 8 + tg];
                pa[mt][2] = Ps[warp][mt * 16 + g]    [kk * 8 + tg + 4];
                pa[mt][3] = Ps[warp][mt * 16 + 8 + g][kk * 8 + tg + 4];
            }
            uint32_t vb[8][2];
            #pragma unroll
            for (int nd = 0; nd < 8; nd++) {
                vb[nd][0] = Vs[kk * 8 + tg]    [nd * 8 + g];
                vb[nd][1] = Vs[kk * 8 + tg + 4][nd * 8 + g];
            }
            #pragma unroll
            for (int mt = 0; mt < 2; mt++)
                #pragma unroll
                for (int nd = 0; nd < 8; nd++)
                    mma_tf32(o[mt][nd], pa[mt], vb[nd]);
        }
        __syncwarp();
    }

    // epilogue: normalize and store
    float inv[4];
    #pragma unroll
    for (int i = 0; i < 4; i++) inv[i] = 1.0f / lr[i];

    #pragma unroll
    for (int mt = 0; mt < 2; mt++) {
        #pragma unroll
        for (int half = 0; half < 2; half++) {
            long row = (long)stage * TOK + (long)b * NSEQ + mrow + mt * 16 + g + half * 8;
            float sc = inv[mt * 2 + half];
            float* op = g_arena + OFF_O + row * CDIM + hh * HDIM;
            #pragma unroll
            for (int nd = 0; nd < 8; nd++) {
                float2 v;
                v.x = o[mt][nd][half * 2 + 0] * sc;
                v.y = o[mt][nd][half * 2 + 1] * sc;
                *(float2*)&op[nd * 8 + tg * 2] = v;
            }
        }
    }
}

// ---------------- combine: x1 = x + sum_i fw[i]*(p_i + proj_b_i) ----------------
__global__ void combine_kernel(const float* __restrict__ x, const float* __restrict__ pb,
                               const float* __restrict__ fw)
{
    long idx = (long)blockIdx.x * 256 + threadIdx.x;
    int c = (int)(idx % CDIM);
    const float* p = g_arena + OFF_P;
    float f0 = __ldg(&fw[0]), f1 = __ldg(&fw[1]), f2 = __ldg(&fw[2]);
    float v = x[idx];
    v = fmaf(f0, p[idx]           + pb[c],            v);
    v = fmaf(f1, p[TOKC + idx]    + pb[CDIM + c],     v);
    v = fmaf(f2, p[2*TOKC + idx]  + pb[2*CDIM + c],   v);
    g_arena[OFF_X1 + idx] = v;
}

// ---------------- launch ----------------
extern "C" void kernel_launch(void* const* d_in, const int* in_sizes, int n_in,
                              void* d_out, int out_size)
{
    const float* x      = (const float*)d_in[0];
    const float* qkv_w  = (const float*)d_in[1];
    const float* proj_w = (const float*)d_in[2];
    const float* proj_b = (const float*)d_in[3];
    const float* ln1_w  = (const float*)d_in[4];
    const float* ln1_b  = (const float*)d_in[5];
    const float* ln2_w  = (const float*)d_in[6];
    const float* ln2_b  = (const float*)d_in[7];
    const float* mlp_w1 = (const float*)d_in[8];
    const float* mlp_b1 = (const float*)d_in[9];
    const float* mlp_w2 = (const float*)d_in[10];
    const float* mlp_b2 = (const float*)d_in[11];
    const float* fw     = (const float*)d_in[12];
    float* out = (float*)d_out;

    // 1) h = LN1(x)
    ln_kernel<<<TOK, 256>>>(x, 0, ln1_w, ln1_b, OFF_H);

    // 2) qkv(all stages) = h @ qkv_w_all^T   [8192 x 6912]
    mma_gemm<0><<<dim3(QKVW / 128, TOK / 128, 1), 256>>>(
        OFF_H, qkv_w, OFF_QKV, nullptr, nullptr, 0, CDIM, QKVW, 0, 0, 0);

    // 3) attention, all stages (tensor-core)
    attn_mma_kernel<<<dim3(NSEQ / 128, HNUM, STAGES * BATCH), 128>>>();

    // 4) p_i = o_i @ proj_w_i^T (batched over stage)
    mma_gemm<0><<<dim3(CDIM / 128, TOK / 128, STAGES), 256>>>(
        OFF_O, proj_w, OFF_P, nullptr, nullptr, 0, CDIM, CDIM,
        TOKC, (long)CDIM * CDIM, TOKC);

    // 5) x1 = x + sum_i fw[i]*(p_i + proj_b_i)
    combine_kernel<<<(int)(TOKC / 256), 256>>>(x, proj_b, fw);

    // 6) h2 = LN2(x1)
    ln_kernel<<<TOK, 256>>>(nullptr, OFF_X1, ln2_w, ln2_b, OFF_H2);

    // 7) g = gelu(h2 @ mlp_w1^T + b1)   [8192 x 3072]
    mma_gemm<2><<<dim3(MLPH / 128, TOK / 128, 1), 256>>>(
        OFF_H2, mlp_w1, OFF_G, nullptr, mlp_b1, 0, CDIM, MLPH, 0, 0, 0);

    // 8) out = x1 + g @ mlp_w2^T + b2
    mma_gemm<3><<<dim3(CDIM / 128, TOK / 128, 1), 256>>>(
        OFF_G, mlp_w2, 0, out, mlp_b2, OFF_X1, MLPH, CDIM, 0, 0, 0);
}

// round 7
// speedup vs baseline: 1.9849x; 1.0191x over previous
#include <cuda_runtime.h>
#include <math.h>
#include <stdint.h>

// ---------------- problem constants ----------------
#define TOK    8192        // B*N
#define CDIM   768
#define HNUM   12
#define HDIM   64
#define NSEQ   1024
#define BATCH  8
#define MLPH   3072
#define QKVW   6912        // 3 stages * 3*C
#define STAGES 3

constexpr long TOKC   = (long)TOK * CDIM;
constexpr long OFF_H   = 0;
constexpr long OFF_QKV = OFF_H   + TOKC;
constexpr long OFF_O   = OFF_QKV + (long)TOK*QKVW;
constexpr long OFF_P   = OFF_O   + 3*TOKC;
constexpr long OFF_X1  = OFF_P   + 3*TOKC;
constexpr long OFF_H2  = OFF_X1  + TOKC;
constexpr long OFF_G   = OFF_H2  + TOKC;
constexpr long ARENA_SZ = OFF_G  + (long)TOK*MLPH;

__device__ float g_arena[ARENA_SZ];

// ---------------- helpers ----------------
__device__ __forceinline__ uint32_t f2tf32(float f) {
    uint32_t o;
    asm("cvt.rna.tf32.f32 %0, %1;" : "=r"(o) : "f"(f));
    return o;
}

__device__ __forceinline__ uint32_t smem_u32(const void* p) {
    uint32_t a;
    asm("{ .reg .u64 t; cvta.to.shared.u64 t, %1; cvt.u32.u64 %0, t; }" : "=r"(a) : "l"(p));
    return a;
}

__device__ __forceinline__ void mma_tf32(float* c, const uint32_t* a, const uint32_t* b) {
    asm volatile(
        "mma.sync.aligned.m16n8k8.row.col.f32.tf32.tf32.f32 "
        "{%0,%1,%2,%3}, {%4,%5,%6,%7}, {%8,%9}, {%0,%1,%2,%3};\n"
        : "+f"(c[0]), "+f"(c[1]), "+f"(c[2]), "+f"(c[3])
        : "r"(a[0]), "r"(a[1]), "r"(a[2]), "r"(a[3]), "r"(b[0]), "r"(b[1]));
}

__device__ __forceinline__ void ldsm_x4(uint32_t* r, uint32_t addr) {
    asm volatile("ldmatrix.sync.aligned.m8n8.x4.shared.b16 {%0,%1,%2,%3}, [%4];"
        : "=r"(r[0]), "=r"(r[1]), "=r"(r[2]), "=r"(r[3]) : "r"(addr));
}
__device__ __forceinline__ void ldsm_x2(uint32_t* r, uint32_t addr) {
    asm volatile("ldmatrix.sync.aligned.m8n8.x2.shared.b16 {%0,%1}, [%2];"
        : "=r"(r[0]), "=r"(r[1]) : "r"(addr));
}

__device__ __forceinline__ float gelu_f(float v) {
    return 0.5f * v * (1.0f + erff(v * 0.70710678118654752440f));
}

// ---------------- layernorm ----------------
__global__ void ln_kernel(const float* __restrict__ xext, long xOff,
                          const float* __restrict__ w, const float* __restrict__ b,
                          long outOff)
{
    int row = blockIdx.x;
    const float* xr = (xext ? xext : (const float*)(g_arena + xOff)) + (long)row * CDIM;
    int t = threadIdx.x;
    float v0 = xr[t], v1 = xr[t + 256], v2 = xr[t + 512];
    float s = v0 + v1 + v2;

    __shared__ float red[8];
    #pragma unroll
    for (int o = 16; o > 0; o >>= 1) s += __shfl_xor_sync(0xffffffffu, s, o);
    if ((t & 31) == 0) red[t >> 5] = s;
    __syncthreads();
    float tot = red[0]+red[1]+red[2]+red[3]+red[4]+red[5]+red[6]+red[7];
    float mu = tot * (1.0f / CDIM);

    float d0 = v0 - mu, d1 = v1 - mu, d2 = v2 - mu;
    float q = d0*d0 + d1*d1 + d2*d2;
    #pragma unroll
    for (int o = 16; o > 0; o >>= 1) q += __shfl_xor_sync(0xffffffffu, q, o);
    __syncthreads();
    if ((t & 31) == 0) red[t >> 5] = q;
    __syncthreads();
    float qt = red[0]+red[1]+red[2]+red[3]+red[4]+red[5]+red[6]+red[7];
    float inv = rsqrtf(qt * (1.0f / CDIM) + 1e-5f);

    float* op = g_arena + outOff + (long)row * CDIM;
    op[t      ] = d0 * inv * w[t      ] + b[t      ];
    op[t + 256] = d1 * inv * w[t + 256] + b[t + 256];
    op[t + 512] = d2 * inv * w[t + 512] + b[t + 512];
}

// ---------------- TF32 mma.sync GEMM with ldmatrix fragments ----------------
// 128x128 tile, BK=16, 256 threads (8 warps, 2x4 warp grid, 64x32 warp tile).
// Smem m-major [row][16k] stride 20 (stride/16B=5 odd -> ldmatrix rows conflict-free).
// A-frag: ldmatrix.x4, B-frag: ldmatrix.x2. Register-prefetch double buffering.
// MODE 0: C = acc;  MODE 2: C = gelu(acc+bias);  MODE 3: C = res + acc + bias (into Cext)
#define RSTR 20                       // row stride in words
#define STAGE_B (128 * RSTR * 4)      // bytes per buffer per operand

template<int MODE>
__global__ __launch_bounds__(256)
void mma_gemm(long aOff, const float* __restrict__ Wt, long cOff, float* __restrict__ Cext,
              const float* __restrict__ bias, long resOff,
              int K, int Nout, long aStride, long wStride, long cStride)
{
    const float* A = g_arena + aOff + (long)blockIdx.z * aStride;
    const float* W = Wt + (long)blockIdx.z * wStride;
    float* Cp = Cext ? Cext : (g_arena + cOff + (long)blockIdx.z * cStride);

    int m0 = blockIdx.y * 128;
    int n0 = blockIdx.x * 128;
    int tid = threadIdx.x, lane = tid & 31, wid = tid >> 5;
    int wm = (wid & 1) * 64;
    int wn = (wid >> 1) * 32;
    int g = lane >> 2, tg = lane & 3;

    __shared__ uint32_t As[2][128][RSTR];
    __shared__ uint32_t Bs[2][128][RSTR];
    uint32_t sbA = smem_u32(As);
    uint32_t sbB = smem_u32(Bs);

    // ldmatrix per-lane row addresses
    int r8 = lane & 7, t4 = lane >> 3;
    uint32_t a_base = sbA + (uint32_t)(((wm + r8 + (t4 & 1) * 8) * RSTR + (t4 >> 1) * 4) * 4);
    uint32_t b_base = sbB + (uint32_t)(((wn + r8) * RSTR + (t4 & 1) * 4) * 4);

    float c[4][4][4] = {};

    // gmem load mapping: row = tid&127, 2 float4 at k = q0, q0+8 (q0 = (tid>>7)*4)
    int lrow = tid & 127;
    int q0 = (tid >> 7) * 4;

    const float* arow = &A[(long)(m0 + lrow) * K + q0];
    const float* brow = &W[(long)(n0 + lrow) * K + q0];

    // tile 0 -> smem (STS.128, tf32-converted)
    {
        float4 a0 = *(const float4*)arow;
        float4 a1 = *(const float4*)(arow + 8);
        float4 b0 = *(const float4*)brow;
        float4 b1 = *(const float4*)(brow + 8);
        uint4 ua0 = { f2tf32(a0.x), f2tf32(a0.y), f2tf32(a0.z), f2tf32(a0.w) };
        uint4 ua1 = { f2tf32(a1.x), f2tf32(a1.y), f2tf32(a1.z), f2tf32(a1.w) };
        uint4 ub0 = { f2tf32(b0.x), f2tf32(b0.y), f2tf32(b0.z), f2tf32(b0.w) };
        uint4 ub1 = { f2tf32(b1.x), f2tf32(b1.y), f2tf32(b1.z), f2tf32(b1.w) };
        *(uint4*)&As[0][lrow][q0]     = ua0;
        *(uint4*)&As[0][lrow][q0 + 8] = ua1;
        *(uint4*)&Bs[0][lrow][q0]     = ub0;
        *(uint4*)&Bs[0][lrow][q0 + 8] = ub1;
    }
    __syncthreads();

    int nk = K >> 4;
    int buf = 0;
    for (int kt = 0; kt < nk; ++kt) {
        float4 pa0, pa1, pb0, pb1;
        bool pre = (kt + 1 < nk);
        if (pre) {
            const float* an = arow + (kt + 1) * 16;
            const float* bn = brow + (kt + 1) * 16;
            pa0 = *(const float4*)an;
            pa1 = *(const float4*)(an + 8);
            pb0 = *(const float4*)bn;
            pb1 = *(const float4*)(bn + 8);
        }

        uint32_t abuf = a_base + (uint32_t)(buf * STAGE_B);
        uint32_t bbuf = b_base + (uint32_t)(buf * STAGE_B);
        #pragma unroll
        for (int ks = 0; ks < 2; ks++) {
            uint32_t af[4][4];
            #pragma unroll
            for (int mt = 0; mt < 4; mt++)
                ldsm_x4(af[mt], abuf + mt * (16 * RSTR * 4) + ks * 32);
            uint32_t bfr[4][2];
            #pragma unroll
            for (int nt = 0; nt < 4; nt++)
                ldsm_x2(bfr[nt], bbuf + nt * (8 * RSTR * 4) + ks * 32);
            #pragma unroll
            for (int mt = 0; mt < 4; mt++)
                #pragma unroll
                for (int nt = 0; nt < 4; nt++)
                    mma_tf32(c[mt][nt], af[mt], bfr[nt]);
        }

        if (pre) {
            int nb = buf ^ 1;
            uint4 ua0 = { f2tf32(pa0.x), f2tf32(pa0.y), f2tf32(pa0.z), f2tf32(pa0.w) };
            uint4 ua1 = { f2tf32(pa1.x), f2tf32(pa1.y), f2tf32(pa1.z), f2tf32(pa1.w) };
            uint4 ub0 = { f2tf32(pb0.x), f2tf32(pb0.y), f2tf32(pb0.z), f2tf32(pb0.w) };
            uint4 ub1 = { f2tf32(pb1.x), f2tf32(pb1.y), f2tf32(pb1.z), f2tf32(pb1.w) };
            *(uint4*)&As[nb][lrow][q0]     = ua0;
            *(uint4*)&As[nb][lrow][q0 + 8] = ua1;
            *(uint4*)&Bs[nb][lrow][q0]     = ub0;
            *(uint4*)&Bs[nb][lrow][q0 + 8] = ub1;
            __syncthreads();
            buf = nb;
        }
    }

    // epilogue: c[mt][nt]: rows m0+wm+mt*16+g(+8), cols n0+wn+nt*8+tg*2(+1)
    #pragma unroll
    for (int mt = 0; mt < 4; mt++) {
        #pragma unroll
        for (int half = 0; half < 2; half++) {
            long row = m0 + wm + mt * 16 + g + half * 8;
            #pragma unroll
            for (int nt = 0; nt < 4; nt++) {
                int col = n0 + wn + nt * 8 + tg * 2;
                float v0 = c[mt][nt][half * 2 + 0];
                float v1 = c[mt][nt][half * 2 + 1];
                if (MODE == 2) {
                    v0 = gelu_f(v0 + bias[col]);
                    v1 = gelu_f(v1 + bias[col + 1]);
                } else if (MODE == 3) {
                    float2 r = *(const float2*)&g_arena[resOff + row * (long)Nout + col];
                    v0 = r.x + v0 + bias[col];
                    v1 = r.y + v1 + bias[col + 1];
                }
                float2 o; o.x = v0; o.y = v1;
                *(float2*)&Cp[row * (long)Nout + col] = o;
            }
        }
    }
}

// ---------------- tensor-core flash attention (unchanged from R6 passing) ----------------
#define ATK 32

__global__ __launch_bounds__(128)
void attn_mma_kernel()
{
    int z = blockIdx.z;
    int b = z & 7;
    int stage = z >> 3;
    int hh = blockIdx.y;
    int q0 = blockIdx.x * 128;
    int tid = threadIdx.x;
    int warp = tid >> 5, lane = tid & 31;
    int g = lane >> 2, tg = lane & 3;

    const float* qbase = g_arena + OFF_QKV + (long)(b * NSEQ) * QKVW + stage * 2304 + hh * HDIM;
    const float* kbase = qbase + CDIM;
    const float* vbase = qbase + 2 * CDIM;

    __shared__ uint32_t Ks[ATK][68];
    __shared__ uint32_t Vs[ATK][72];
    __shared__ uint32_t Ps[4][32][36];

    uint32_t qa[2][8][4];
    int mrow = q0 + warp * 32;
    #pragma unroll
    for (int mt = 0; mt < 2; mt++) {
        #pragma unroll
        for (int ks = 0; ks < 8; ks++) {
            const float* r0 = qbase + (long)(mrow + mt * 16 + g) * QKVW + ks * 8 + tg;
            const float* r1 = r0 + 8 * QKVW;
            qa[mt][ks][0] = f2tf32(0.125f * __ldg(r0));
            qa[mt][ks][1] = f2tf32(0.125f * __ldg(r1));
            qa[mt][ks][2] = f2tf32(0.125f * __ldg(r0 + 4));
            qa[mt][ks][3] = f2tf32(0.125f * __ldg(r1 + 4));
        }
    }

    float o[2][8][4] = {};
    float mr[4] = {-1e30f, -1e30f, -1e30f, -1e30f};
    float lr[4] = {0.f, 0.f, 0.f, 0.f};

    for (int k0 = 0; k0 < NSEQ; k0 += ATK) {
        __syncthreads();
        {
            int row = tid & 31, cs = tid >> 5;
            const float* kp = kbase + (long)(k0 + row) * QKVW + cs * 16;
            const float* vp = vbase + (long)(k0 + row) * QKVW + cs * 16;
            #pragma unroll
            for (int j = 0; j < 4; j++) {
                float4 kv = *(const float4*)(kp + j * 4);
                float4 vv = *(const float4*)(vp + j * 4);
                int cb = cs * 16 + j * 4;
                Ks[row][cb+0] = f2tf32(kv.x); Ks[row][cb+1] = f2tf32(kv.y);
                Ks[row][cb+2] = f2tf32(kv.z); Ks[row][cb+3] = f2tf32(kv.w);
                Vs[row][cb+0] = f2tf32(vv.x); Vs[row][cb+1] = f2tf32(vv.y);
                Vs[row][cb+2] = f2tf32(vv.z); Vs[row][cb+3] = f2tf32(vv.w);
            }
        }
        __syncthreads();

        float c[2][4][4] = {};
        #pragma unroll
        for (int ks = 0; ks < 8; ks++) {
            uint32_t kb_[4][2];
            #pragma unroll
            for (int nt = 0; nt < 4; nt++) {
                kb_[nt][0] = Ks[nt * 8 + g][ks * 8 + tg];
                kb_[nt][1] = Ks[nt * 8 + g][ks * 8 + tg + 4];
            }
            #pragma unroll
            for (int mt = 0; mt < 2; mt++)
                #pragma unroll
                for (int nt = 0; nt < 4; nt++)
                    mma_tf32(c[mt][nt], qa[mt][ks], kb_[nt]);
        }

        float tm[4] = {-1e30f, -1e30f, -1e30f, -1e30f};
        #pragma unroll
        for (int mt = 0; mt < 2; mt++)
            #pragma unroll
            for (int nt = 0; nt < 4; nt++)
                #pragma unroll
                for (int r = 0; r < 4; r++)
                    tm[mt * 2 + (r >> 1)] = fmaxf(tm[mt * 2 + (r >> 1)], c[mt][nt][r]);
        #pragma unroll
        for (int i = 0; i < 4; i++) {
            tm[i] = fmaxf(tm[i], __shfl_xor_sync(0xffffffffu, tm[i], 1));
            tm[i] = fmaxf(tm[i], __shfl_xor_sync(0xffffffffu, tm[i], 2));
        }
        float mn[4], corr[4];
        #pragma unroll
        for (int i = 0; i < 4; i++) {
            mn[i] = fmaxf(mr[i], tm[i]);
            corr[i] = __expf(mr[i] - mn[i]);
        }
        float ts[4] = {0.f, 0.f, 0.f, 0.f};
        #pragma unroll
        for (int mt = 0; mt < 2; mt++)
            #pragma unroll
            for (int nt = 0; nt < 4; nt++)
                #pragma unroll
                for (int r = 0; r < 4; r++) {
                    int i = mt * 2 + (r >> 1);
                    float p = __expf(c[mt][nt][r] - mn[i]);
                    c[mt][nt][r] = p;
                    ts[i] += p;
                }
        #pragma unroll
        for (int i = 0; i < 4; i++) {
            ts[i] += __shfl_xor_sync(0xffffffffu, ts[i], 1);
            ts[i] += __shfl_xor_sync(0xffffffffu, ts[i], 2);
            lr[i] = lr[i] * corr[i] + ts[i];
            mr[i] = mn[i];
        }
        #pragma unroll
        for (int mt = 0; mt < 2; mt++)
            #pragma unroll
            for (int nd = 0; nd < 8; nd++)
                #pragma unroll
                for (int r = 0; r < 4; r++)
                    o[mt][nd][r] *= corr[mt * 2 + (r >> 1)];

        #pragma unroll
        for (int mt = 0; mt < 2; mt++)
            #pragma unroll
            for (int nt = 0; nt < 4; nt++) {
                int r0 = mt * 16 + g, col = nt * 8 + tg * 2;
                uint2 p0, p1;
                p0.x = f2tf32(c[mt][nt][0]); p0.y = f2tf32(c[mt][nt][1]);
                p1.x = f2tf32(c[mt][nt][2]); p1.y = f2tf32(c[mt][nt][3]);
                *(uint2*)&Ps[warp][r0][col]     = p0;
                *(uint2*)&Ps[warp][r0 + 8][col] = p1;
            }
        __syncwarp();

        #pragma unroll
        for (int kk = 0; kk < 4; kk++) {
            uint32_t pa[2][4];
            #pragma unroll
            for (int mt = 0; mt < 2; mt++) {
                pa[mt][0] = Ps[warp][mt * 16 + g]    [kk * 8 + tg];
                pa[mt][1] = Ps[warp][mt * 16 + 8 + g][kk * 8 + tg];
                pa[mt][2] = Ps[warp][mt * 16 + g]    [kk * 8 + tg + 4];
                pa[mt][3] = Ps[warp][mt * 16 + 8 + g][kk * 8 + tg + 4];
            }
            uint32_t vb[8][2];
            #pragma unroll
            for (int nd = 0; nd < 8; nd++) {
                vb[nd][0] = Vs[kk * 8 + tg]    [nd * 8 + g];
                vb[nd][1] = Vs[kk * 8 + tg + 4][nd * 8 + g];
            }
            #pragma unroll
            for (int mt = 0; mt < 2; mt++)
                #pragma unroll
                for (int nd = 0; nd < 8; nd++)
                    mma_tf32(o[mt][nd], pa[mt], vb[nd]);
        }
        __syncwarp();
    }

    float inv[4];
    #pragma unroll
    for (int i = 0; i < 4; i++) inv[i] = 1.0f / lr[i];

    #pragma unroll
    for (int mt = 0; mt < 2; mt++) {
        #pragma unroll
        for (int half = 0; half < 2; half++) {
            long row = (long)stage * TOK + (long)b * NSEQ + mrow + mt * 16 + g + half * 8;
            float sc = inv[mt * 2 + half];
            float* op = g_arena + OFF_O + row * CDIM + hh * HDIM;
            #pragma unroll
            for (int nd = 0; nd < 8; nd++) {
                float2 v;
                v.x = o[mt][nd][half * 2 + 0] * sc;
                v.y = o[mt][nd][half * 2 + 1] * sc;
                *(float2*)&op[nd * 8 + tg * 2] = v;
            }
        }
    }
}

// ---------------- combine: x1 = x + sum_i fw[i]*(p_i + proj_b_i) ----------------
__global__ void combine_kernel(const float* __restrict__ x, const float* __restrict__ pb,
                               const float* __restrict__ fw)
{
    long idx = (long)blockIdx.x * 256 + threadIdx.x;
    int c = (int)(idx % CDIM);
    const float* p = g_arena + OFF_P;
    float f0 = __ldg(&fw[0]), f1 = __ldg(&fw[1]), f2 = __ldg(&fw[2]);
    float v = x[idx];
    v = fmaf(f0, p[idx]           + pb[c],            v);
    v = fmaf(f1, p[TOKC + idx]    + pb[CDIM + c],     v);
    v = fmaf(f2, p[2*TOKC + idx]  + pb[2*CDIM + c],   v);
    g_arena[OFF_X1 + idx] = v;
}

// ---------------- launch ----------------
extern "C" void kernel_launch(void* const* d_in, const int* in_sizes, int n_in,
                              void* d_out, int out_size)
{
    const float* x      = (const float*)d_in[0];
    const float* qkv_w  = (const float*)d_in[1];
    const float* proj_w = (const float*)d_in[2];
    const float* proj_b = (const float*)d_in[3];
    const float* ln1_w  = (const float*)d_in[4];
    const float* ln1_b  = (const float*)d_in[5];
    const float* ln2_w  = (const float*)d_in[6];
    const float* ln2_b  = (const float*)d_in[7];
    const float* mlp_w1 = (const float*)d_in[8];
    const float* mlp_b1 = (const float*)d_in[9];
    const float* mlp_w2 = (const float*)d_in[10];
    const float* mlp_b2 = (const float*)d_in[11];
    const float* fw     = (const float*)d_in[12];
    float* out = (float*)d_out;

    // 1) h = LN1(x)
    ln_kernel<<<TOK, 256>>>(x, 0, ln1_w, ln1_b, OFF_H);

    // 2) qkv(all stages) = h @ qkv_w_all^T   [8192 x 6912]
    mma_gemm<0><<<dim3(QKVW / 128, TOK / 128, 1), 256>>>(
        OFF_H, qkv_w, OFF_QKV, nullptr, nullptr, 0, CDIM, QKVW, 0, 0, 0);

    // 3) attention, all stages (tensor-core)
    attn_mma_kernel<<<dim3(NSEQ / 128, HNUM, STAGES * BATCH), 128>>>();

    // 4) p_i = o_i @ proj_w_i^T (batched over stage)
    mma_gemm<0><<<dim3(CDIM / 128, TOK / 128, STAGES), 256>>>(
        OFF_O, proj_w, OFF_P, nullptr, nullptr, 0, CDIM, CDIM,
        TOKC, (long)CDIM * CDIM, TOKC);

    // 5) x1 = x + sum_i fw[i]*(p_i + proj_b_i)
    combine_kernel<<<(int)(TOKC / 256), 256>>>(x, proj_b, fw);

    // 6) h2 = LN2(x1)
    ln_kernel<<<TOK, 256>>>(nullptr, OFF_X1, ln2_w, ln2_b, OFF_H2);

    // 7) g = gelu(h2 @ mlp_w1^T + b1)   [8192 x 3072]
    mma_gemm<2><<<dim3(MLPH / 128, TOK / 128, 1), 256>>>(
        OFF_H2, mlp_w1, OFF_G, nullptr, mlp_b1, 0, CDIM, MLPH, 0, 0, 0);

    // 8) out = x1 + g @ mlp_w2^T + b2
    mma_gemm<3><<<dim3(CDIM / 128, TOK / 128, 1), 256>>>(
        OFF_G, mlp_w2, 0, out, mlp_b2, OFF_X1, MLPH, CDIM, 0, 0, 0);
}

// round 8
// speedup vs baseline: 2.3515x; 1.1847x over previous
#include <cuda_runtime.h>
#include <math.h>
#include <stdint.h>

// ---------------- problem constants ----------------
#define TOK    8192        // B*N
#define CDIM   768
#define HNUM   12
#define HDIM   64
#define NSEQ   1024
#define BATCH  8
#define MLPH   3072
#define QKVW   6912        // 3 stages * 3*C
#define STAGES 3

constexpr long TOKC   = (long)TOK * CDIM;
constexpr long OFF_H   = 0;
constexpr long OFF_QKV = OFF_H   + TOKC;
constexpr long OFF_O   = OFF_QKV + (long)TOK*QKVW;
constexpr long OFF_P   = OFF_O   + 3*TOKC;
constexpr long OFF_X1  = OFF_P   + 3*TOKC;
constexpr long OFF_H2  = OFF_X1  + TOKC;
constexpr long OFF_G   = OFF_H2  + TOKC;
// tf32-rounded weight copies
constexpr long OFF_WQ  = OFF_G  + (long)TOK*MLPH;
constexpr long OFF_WP  = OFF_WQ + (long)QKVW*CDIM;
constexpr long OFF_W1  = OFF_WP + (long)STAGES*CDIM*CDIM;
constexpr long OFF_W2  = OFF_W1 + (long)MLPH*CDIM;
constexpr long ARENA_SZ = OFF_W2 + (long)CDIM*MLPH;

__device__ float g_arena[ARENA_SZ];

// ---------------- helpers ----------------
__device__ __forceinline__ uint32_t f2tf32(float f) {
    uint32_t o;
    asm("cvt.rna.tf32.f32 %0, %1;" : "=r"(o) : "f"(f));
    return o;
}
__device__ __forceinline__ float round_tf32(float f) {
    return __uint_as_float(f2tf32(f));
}

__device__ __forceinline__ uint32_t smem_u32(const void* p) {
    uint32_t a;
    asm("{ .reg .u64 t; cvta.to.shared.u64 t, %1; cvt.u32.u64 %0, t; }" : "=r"(a) : "l"(p));
    return a;
}

__device__ __forceinline__ void mma_tf32(float* c, const uint32_t* a, const uint32_t* b) {
    asm volatile(
        "mma.sync.aligned.m16n8k8.row.col.f32.tf32.tf32.f32 "
        "{%0,%1,%2,%3}, {%4,%5,%6,%7}, {%8,%9}, {%0,%1,%2,%3};\n"
        : "+f"(c[0]), "+f"(c[1]), "+f"(c[2]), "+f"(c[3])
        : "r"(a[0]), "r"(a[1]), "r"(a[2]), "r"(a[3]), "r"(b[0]), "r"(b[1]));
}

__device__ __forceinline__ void ldsm_x4(uint32_t* r, uint32_t addr) {
    asm volatile("ldmatrix.sync.aligned.m8n8.x4.shared.b16 {%0,%1,%2,%3}, [%4];"
        : "=r"(r[0]), "=r"(r[1]), "=r"(r[2]), "=r"(r[3]) : "r"(addr));
}
__device__ __forceinline__ void ldsm_x2(uint32_t* r, uint32_t addr) {
    asm volatile("ldmatrix.sync.aligned.m8n8.x2.shared.b16 {%0,%1}, [%2];"
        : "=r"(r[0]), "=r"(r[1]) : "r"(addr));
}

__device__ __forceinline__ void cp16(uint32_t saddr, const float* g) {
    asm volatile("cp.async.cg.shared.global [%0], [%1], 16;" :: "r"(saddr), "l"(g));
}

__device__ __forceinline__ float gelu_f(float v) {
    return 0.5f * v * (1.0f + erff(v * 0.70710678118654752440f));
}

// ---------------- weight tf32 rounding (producer-side conversion) ----------------
__global__ void tf32_round_kernel(const float* __restrict__ src, long dstOff, int n4)
{
    int i = blockIdx.x * 256 + threadIdx.x;
    if (i < n4) {
        float4 v = ((const float4*)src)[i];
        uint4 u = { f2tf32(v.x), f2tf32(v.y), f2tf32(v.z), f2tf32(v.w) };
        ((uint4*)(g_arena + dstOff))[i] = u;
    }
}

// ---------------- layernorm (outputs tf32-rounded; they only feed GEMMs) ----------------
__global__ void ln_kernel(const float* __restrict__ xext, long xOff,
                          const float* __restrict__ w, const float* __restrict__ b,
                          long outOff)
{
    int row = blockIdx.x;
    const float* xr = (xext ? xext : (const float*)(g_arena + xOff)) + (long)row * CDIM;
    int t = threadIdx.x;
    float v0 = xr[t], v1 = xr[t + 256], v2 = xr[t + 512];
    float s = v0 + v1 + v2;

    __shared__ float red[8];
    #pragma unroll
    for (int o = 16; o > 0; o >>= 1) s += __shfl_xor_sync(0xffffffffu, s, o);
    if ((t & 31) == 0) red[t >> 5] = s;
    __syncthreads();
    float tot = red[0]+red[1]+red[2]+red[3]+red[4]+red[5]+red[6]+red[7];
    float mu = tot * (1.0f / CDIM);

    float d0 = v0 - mu, d1 = v1 - mu, d2 = v2 - mu;
    float q = d0*d0 + d1*d1 + d2*d2;
    #pragma unroll
    for (int o = 16; o > 0; o >>= 1) q += __shfl_xor_sync(0xffffffffu, q, o);
    __syncthreads();
    if ((t & 31) == 0) red[t >> 5] = q;
    __syncthreads();
    float qt = red[0]+red[1]+red[2]+red[3]+red[4]+red[5]+red[6]+red[7];
    float inv = rsqrtf(qt * (1.0f / CDIM) + 1e-5f);

    float* op = g_arena + outOff + (long)row * CDIM;
    op[t      ] = round_tf32(d0 * inv * w[t      ] + b[t      ]);
    op[t + 256] = round_tf32(d1 * inv * w[t + 256] + b[t + 256]);
    op[t + 512] = round_tf32(d2 * inv * w[t + 512] + b[t + 512]);
}

// ---------------- TF32 mma.sync GEMM: cp.async 2-stage + ldmatrix ----------------
// 128x128 tile, BK=16, 256 threads (8 warps, 2x4 warp grid, 64x32 warp tile).
// Inputs pre-rounded to tf32 (weights via tf32_round_kernel, activations by producers).
// Smem m-major [row][16k] stride 20; A-frag ldmatrix.x4, B-frag ldmatrix.x2.
// MODE 0: C = acc;  MODE 2: C = round_tf32(gelu(acc+bias));  MODE 3: C = res+acc+bias (Cext)
#define RSTR 20                       // row stride in words
#define STAGE_B (128 * RSTR * 4)      // bytes per buffer per operand

template<int MODE>
__global__ __launch_bounds__(256, 2)
void mma_gemm(long aOff, long wOff, long cOff, float* __restrict__ Cext,
              const float* __restrict__ bias, long resOff,
              int K, int Nout, long aStride, long wStride, long cStride)
{
    const float* A = g_arena + aOff + (long)blockIdx.z * aStride;
    const float* W = g_arena + wOff + (long)blockIdx.z * wStride;
    float* Cp = Cext ? Cext : (g_arena + cOff + (long)blockIdx.z * cStride);

    int m0 = blockIdx.y * 128;
    int n0 = blockIdx.x * 128;
    int tid = threadIdx.x, lane = tid & 31, wid = tid >> 5;
    int wm = (wid & 1) * 64;
    int wn = (wid >> 1) * 32;
    int g = lane >> 2, tg = lane & 3;

    __shared__ uint32_t As[2][128][RSTR];
    __shared__ uint32_t Bs[2][128][RSTR];
    uint32_t sbA = smem_u32(As);
    uint32_t sbB = smem_u32(Bs);

    // ldmatrix per-lane row addresses
    int r8 = lane & 7, t4 = lane >> 3;
    uint32_t a_base = sbA + (uint32_t)(((wm + r8 + (t4 & 1) * 8) * RSTR + (t4 >> 1) * 4) * 4);
    uint32_t b_base = sbB + (uint32_t)(((wn + r8) * RSTR + (t4 & 1) * 4) * 4);

    float c[4][4][4] = {};

    // gmem->smem: row = tid&127, two 16B chunks at words q0 and q0+8 (q0 = (tid>>7)*4)
    int lrow = tid & 127;
    int q0 = (tid >> 7) * 4;
    const float* arow = &A[(long)(m0 + lrow) * K + q0];
    const float* brow = &W[(long)(n0 + lrow) * K + q0];
    uint32_t sa = sbA + (uint32_t)((lrow * RSTR + q0) * 4);
    uint32_t sb = sbB + (uint32_t)((lrow * RSTR + q0) * 4);

    // prologue: stage 0
    cp16(sa, arow);       cp16(sa + 32, arow + 8);
    cp16(sb, brow);       cp16(sb + 32, brow + 8);
    asm volatile("cp.async.commit_group;" ::: "memory");

    int nk = K >> 4;
    int buf = 0;
    for (int kt = 0; kt < nk; ++kt) {
        if (kt + 1 < nk) {
            const float* an = arow + (kt + 1) * 16;
            const float* bn = brow + (kt + 1) * 16;
            uint32_t off = (uint32_t)((buf ^ 1) * STAGE_B);
            cp16(sa + off, an);       cp16(sa + off + 32, an + 8);
            cp16(sb + off, bn);       cp16(sb + off + 32, bn + 8);
            asm volatile("cp.async.commit_group;" ::: "memory");
            asm volatile("cp.async.wait_group 1;" ::: "memory");
        } else {
            asm volatile("cp.async.wait_group 0;" ::: "memory");
        }
        __syncthreads();

        uint32_t abuf = a_base + (uint32_t)(buf * STAGE_B);
        uint32_t bbuf = b_base + (uint32_t)(buf * STAGE_B);
        #pragma unroll
        for (int ks = 0; ks < 2; ks++) {
            uint32_t af[4][4];
            #pragma unroll
            for (int mt = 0; mt < 4; mt++)
                ldsm_x4(af[mt], abuf + mt * (16 * RSTR * 4) + ks * 32);
            uint32_t bfr[4][2];
            #pragma unroll
            for (int nt = 0; nt < 4; nt++)
                ldsm_x2(bfr[nt], bbuf + nt * (8 * RSTR * 4) + ks * 32);
            #pragma unroll
            for (int mt = 0; mt < 4; mt++)
                #pragma unroll
                for (int nt = 0; nt < 4; nt++)
                    mma_tf32(c[mt][nt], af[mt], bfr[nt]);
        }
        __syncthreads();   // all readers done before next cp.async overwrites this buffer
        buf ^= 1;
    }

    // epilogue: c[mt][nt]: rows m0+wm+mt*16+g(+8), cols n0+wn+nt*8+tg*2(+1)
    #pragma unroll
    for (int mt = 0; mt < 4; mt++) {
        #pragma unroll
        for (int half = 0; half < 2; half++) {
            long row = m0 + wm + mt * 16 + g + half * 8;
            #pragma unroll
            for (int nt = 0; nt < 4; nt++) {
                int col = n0 + wn + nt * 8 + tg * 2;
                float v0 = c[mt][nt][half * 2 + 0];
                float v1 = c[mt][nt][half * 2 + 1];
                if (MODE == 2) {
                    v0 = round_tf32(gelu_f(v0 + bias[col]));
                    v1 = round_tf32(gelu_f(v1 + bias[col + 1]));
                } else if (MODE == 3) {
                    float2 r = *(const float2*)&g_arena[resOff + row * (long)Nout + col];
                    v0 = r.x + v0 + bias[col];
                    v1 = r.y + v1 + bias[col + 1];
                }
                float2 o; o.x = v0; o.y = v1;
                *(float2*)&Cp[row * (long)Nout + col] = o;
            }
        }
    }
}

// ---------------- tensor-core flash attention (output tf32-rounded; feeds proj GEMM) ----------------
#define ATK 32

__global__ __launch_bounds__(128)
void attn_mma_kernel()
{
    int z = blockIdx.z;
    int b = z & 7;
    int stage = z >> 3;
    int hh = blockIdx.y;
    int q0 = blockIdx.x * 128;
    int tid = threadIdx.x;
    int warp = tid >> 5, lane = tid & 31;
    int g = lane >> 2, tg = lane & 3;

    const float* qbase = g_arena + OFF_QKV + (long)(b * NSEQ) * QKVW + stage * 2304 + hh * HDIM;
    const float* kbase = qbase + CDIM;
    const float* vbase = qbase + 2 * CDIM;

    __shared__ uint32_t Ks[ATK][68];
    __shared__ uint32_t Vs[ATK][72];
    __shared__ uint32_t Ps[4][32][36];

    uint32_t qa[2][8][4];
    int mrow = q0 + warp * 32;
    #pragma unroll
    for (int mt = 0; mt < 2; mt++) {
        #pragma unroll
        for (int ks = 0; ks < 8; ks++) {
            const float* r0 = qbase + (long)(mrow + mt * 16 + g) * QKVW + ks * 8 + tg;
            const float* r1 = r0 + 8 * QKVW;
            qa[mt][ks][0] = f2tf32(0.125f * __ldg(r0));
            qa[mt][ks][1] = f2tf32(0.125f * __ldg(r1));
            qa[mt][ks][2] = f2tf32(0.125f * __ldg(r0 + 4));
            qa[mt][ks][3] = f2tf32(0.125f * __ldg(r1 + 4));
        }
    }

    float o[2][8][4] = {};
    float mr[4] = {-1e30f, -1e30f, -1e30f, -1e30f};
    float lr[4] = {0.f, 0.f, 0.f, 0.f};

    for (int k0 = 0; k0 < NSEQ; k0 += ATK) {
        __syncthreads();
        {
            int row = tid & 31, cs = tid >> 5;
            const float* kp = kbase + (long)(k0 + row) * QKVW + cs * 16;
            const float* vp = vbase + (long)(k0 + row) * QKVW + cs * 16;
            #pragma unroll
            for (int j = 0; j < 4; j++) {
                float4 kv = *(const float4*)(kp + j * 4);
                float4 vv = *(const float4*)(vp + j * 4);
                int cb = cs * 16 + j * 4;
                Ks[row][cb+0] = f2tf32(kv.x); Ks[row][cb+1] = f2tf32(kv.y);
                Ks[row][cb+2] = f2tf32(kv.z); Ks[row][cb+3] = f2tf32(kv.w);
                Vs[row][cb+0] = f2tf32(vv.x); Vs[row][cb+1] = f2tf32(vv.y);
                Vs[row][cb+2] = f2tf32(vv.z); Vs[row][cb+3] = f2tf32(vv.w);
            }
        }
        __syncthreads();

        float c[2][4][4] = {};
        #pragma unroll
        for (int ks = 0; ks < 8; ks++) {
            uint32_t kb_[4][2];
            #pragma unroll
            for (int nt = 0; nt < 4; nt++) {
                kb_[nt][0] = Ks[nt * 8 + g][ks * 8 + tg];
                kb_[nt][1] = Ks[nt * 8 + g][ks * 8 + tg + 4];
            }
            #pragma unroll
            for (int mt = 0; mt < 2; mt++)
                #pragma unroll
                for (int nt = 0; nt < 4; nt++)
                    mma_tf32(c[mt][nt], qa[mt][ks], kb_[nt]);
        }

        float tm[4] = {-1e30f, -1e30f, -1e30f, -1e30f};
        #pragma unroll
        for (int mt = 0; mt < 2; mt++)
            #pragma unroll
            for (int nt = 0; nt < 4; nt++)
                #pragma unroll
                for (int r = 0; r < 4; r++)
                    tm[mt * 2 + (r >> 1)] = fmaxf(tm[mt * 2 + (r >> 1)], c[mt][nt][r]);
        #pragma unroll
        for (int i = 0; i < 4; i++) {
            tm[i] = fmaxf(tm[i], __shfl_xor_sync(0xffffffffu, tm[i], 1));
            tm[i] = fmaxf(tm[i], __shfl_xor_sync(0xffffffffu, tm[i], 2));
        }
        float mn[4], corr[4];
        #pragma unroll
        for (int i = 0; i < 4; i++) {
            mn[i] = fmaxf(mr[i], tm[i]);
            corr[i] = __expf(mr[i] - mn[i]);
        }
        float ts[4] = {0.f, 0.f, 0.f, 0.f};
        #pragma unroll
        for (int mt = 0; mt < 2; mt++)
            #pragma unroll
            for (int nt = 0; nt < 4; nt++)
                #pragma unroll
                for (int r = 0; r < 4; r++) {
                    int i = mt * 2 + (r >> 1);
                    float p = __expf(c[mt][nt][r] - mn[i]);
                    c[mt][nt][r] = p;
                    ts[i] += p;
                }
        #pragma unroll
        for (int i = 0; i < 4; i++) {
            ts[i] += __shfl_xor_sync(0xffffffffu, ts[i], 1);
            ts[i] += __shfl_xor_sync(0xffffffffu, ts[i], 2);
            lr[i] = lr[i] * corr[i] + ts[i];
            mr[i] = mn[i];
        }
        #pragma unroll
        for (int mt = 0; mt < 2; mt++)
            #pragma unroll
            for (int nd = 0; nd < 8; nd++)
                #pragma unroll
                for (int r = 0; r < 4; r++)
                    o[mt][nd][r] *= corr[mt * 2 + (r >> 1)];

        #pragma unroll
        for (int mt = 0; mt < 2; mt++)
            #pragma unroll
            for (int nt = 0; nt < 4; nt++) {
                int r0 = mt * 16 + g, col = nt * 8 + tg * 2;
                uint2 p0, p1;
                p0.x = f2tf32(c[mt][nt][0]); p0.y = f2tf32(c[mt][nt][1]);
                p1.x = f2tf32(c[mt][nt][2]); p1.y = f2tf32(c[mt][nt][3]);
                *(uint2*)&Ps[warp][r0][col]     = p0;
                *(uint2*)&Ps[warp][r0 + 8][col] = p1;
            }
        __syncwarp();

        #pragma unroll
        for (int kk = 0; kk < 4; kk++) {
            uint32_t pa[2][4];
            #pragma unroll
            for (int mt = 0; mt < 2; mt++) {
                pa[mt][0] = Ps[warp][mt * 16 + g]    [kk * 8 + tg];
                pa[mt][1] = Ps[warp][mt * 16 + 8 + g][kk * 8 + tg];
                pa[mt][2] = Ps[warp][mt * 16 + g]    [kk * 8 + tg + 4];
                pa[mt][3] = Ps[warp][mt * 16 + 8 + g][kk * 8 + tg + 4];
            }
            uint32_t vb[8][2];
            #pragma unroll
            for (int nd = 0; nd < 8; nd++) {
                vb[nd][0] = Vs[kk * 8 + tg]    [nd * 8 + g];
                vb[nd][1] = Vs[kk * 8 + tg + 4][nd * 8 + g];
            }
            #pragma unroll
            for (int mt = 0; mt < 2; mt++)
                #pragma unroll
                for (int nd = 0; nd < 8; nd++)
                    mma_tf32(o[mt][nd], pa[mt], vb[nd]);
        }
        __syncwarp();
    }

    float inv[4];
    #pragma unroll
    for (int i = 0; i < 4; i++) inv[i] = 1.0f / lr[i];

    #pragma unroll
    for (int mt = 0; mt < 2; mt++) {
        #pragma unroll
        for (int half = 0; half < 2; half++) {
            long row = (long)stage * TOK + (long)b * NSEQ + mrow + mt * 16 + g + half * 8;
            float sc = inv[mt * 2 + half];
            float* op = g_arena + OFF_O + row * CDIM + hh * HDIM;
            #pragma unroll
            for (int nd = 0; nd < 8; nd++) {
                float2 v;
                v.x = round_tf32(o[mt][nd][half * 2 + 0] * sc);
                v.y = round_tf32(o[mt][nd][half * 2 + 1] * sc);
                *(float2*)&op[nd * 8 + tg * 2] = v;
            }
        }
    }
}

// ---------------- combine: x1 = x + sum_i fw[i]*(p_i + proj_b_i) ----------------
__global__ void combine_kernel(const float* __restrict__ x, const float* __restrict__ pb,
                               const float* __restrict__ fw)
{
    long idx = (long)blockIdx.x * 256 + threadIdx.x;
    int c = (int)(idx % CDIM);
    const float* p = g_arena + OFF_P;
    float f0 = __ldg(&fw[0]), f1 = __ldg(&fw[1]), f2 = __ldg(&fw[2]);
    float v = x[idx];
    v = fmaf(f0, p[idx]           + pb[c],            v);
    v = fmaf(f1, p[TOKC + idx]    + pb[CDIM + c],     v);
    v = fmaf(f2, p[2*TOKC + idx]  + pb[2*CDIM + c],   v);
    g_arena[OFF_X1 + idx] = v;
}

// ---------------- launch ----------------
extern "C" void kernel_launch(void* const* d_in, const int* in_sizes, int n_in,
                              void* d_out, int out_size)
{
    const float* x      = (const float*)d_in[0];
    const float* qkv_w  = (const float*)d_in[1];
    const float* proj_w = (const float*)d_in[2];
    const float* proj_b = (const float*)d_in[3];
    const float* ln1_w  = (const float*)d_in[4];
    const float* ln1_b  = (const float*)d_in[5];
    const float* ln2_w  = (const float*)d_in[6];
    const float* ln2_b  = (const float*)d_in[7];
    const float* mlp_w1 = (const float*)d_in[8];
    const float* mlp_b1 = (const float*)d_in[9];
    const float* mlp_w2 = (const float*)d_in[10];
    const float* mlp_b2 = (const float*)d_in[11];
    const float* fw     = (const float*)d_in[12];
    float* out = (float*)d_out;

    // 0) round weights to tf32 into arena copies
    tf32_round_kernel<<<(QKVW*CDIM/4 + 255)/256, 256>>>(qkv_w, OFF_WQ, QKVW*CDIM/4);
    tf32_round_kernel<<<(STAGES*CDIM*CDIM/4 + 255)/256, 256>>>(proj_w, OFF_WP, STAGES*CDIM*CDIM/4);
    tf32_round_kernel<<<(MLPH*CDIM/4 + 255)/256, 256>>>(mlp_w1, OFF_W1, MLPH*CDIM/4);
    tf32_round_kernel<<<(CDIM*MLPH/4 + 255)/256, 256>>>(mlp_w2, OFF_W2, CDIM*MLPH/4);

    // 1) h = LN1(x)  (tf32-rounded)
    ln_kernel<<<TOK, 256>>>(x, 0, ln1_w, ln1_b, OFF_H);

    // 2) qkv(all stages) = h @ qkv_w_all^T   [8192 x 6912]
    mma_gemm<0><<<dim3(QKVW / 128, TOK / 128, 1), 256>>>(
        OFF_H, OFF_WQ, OFF_QKV, nullptr, nullptr, 0, CDIM, QKVW, 0, 0, 0);

    // 3) attention, all stages (tensor-core)
    attn_mma_kernel<<<dim3(NSEQ / 128, HNUM, STAGES * BATCH), 128>>>();

    // 4) p_i = o_i @ proj_w_i^T (batched over stage)
    mma_gemm<0><<<dim3(CDIM / 128, TOK / 128, STAGES), 256>>>(
        OFF_O, OFF_WP, OFF_P, nullptr, nullptr, 0, CDIM, CDIM,
        TOKC, (long)CDIM * CDIM, TOKC);

    // 5) x1 = x + sum_i fw[i]*(p_i + proj_b_i)
    combine_kernel<<<(int)(TOKC / 256), 256>>>(x, proj_b, fw);

    // 6) h2 = LN2(x1)  (tf32-rounded)
    ln_kernel<<<TOK, 256>>>(nullptr, OFF_X1, ln2_w, ln2_b, OFF_H2);

    // 7) g = gelu(h2 @ mlp_w1^T + b1)   [8192 x 3072]  (tf32-rounded)
    mma_gemm<2><<<dim3(MLPH / 128, TOK / 128, 1), 256>>>(
        OFF_H2, OFF_W1, OFF_G, nullptr, mlp_b1, 0, CDIM, MLPH, 0, 0, 0);

    // 8) out = x1 + g @ mlp_w2^T + b2
    mma_gemm<3><<<dim3(CDIM / 128, TOK / 128, 1), 256>>>(
        OFF_G, OFF_W2, 0, out, mlp_b2, OFF_X1, MLPH, CDIM, 0, 0, 0);
}

// round 11
// speedup vs baseline: 2.4273x; 1.0322x over previous
#include <cuda_runtime.h>
#include <math.h>
#include <stdint.h>

// ---------------- problem constants ----------------
#define TOK    8192        // B*N
#define CDIM   768
#define HNUM   12
#define HDIM   64
#define NSEQ   1024
#define BATCH  8
#define MLPH   3072
#define QKVW   6912        // 3 stages * 3*C
#define STAGES 3

constexpr long TOKC   = (long)TOK * CDIM;
constexpr long OFF_H   = 0;
constexpr long OFF_QKV = OFF_H   + TOKC;
constexpr long OFF_O   = OFF_QKV + (long)TOK*QKVW;
constexpr long OFF_P   = OFF_O   + 3*TOKC;
constexpr long OFF_X1  = OFF_P   + 3*TOKC;
constexpr long OFF_H2  = OFF_X1  + TOKC;
constexpr long OFF_G   = OFF_H2  + TOKC;
// tf32-rounded weight copies
constexpr long OFF_WQ  = OFF_G  + (long)TOK*MLPH;
constexpr long OFF_WP  = OFF_WQ + (long)QKVW*CDIM;
constexpr long OFF_W1  = OFF_WP + (long)STAGES*CDIM*CDIM;
constexpr long OFF_W2  = OFF_W1 + (long)MLPH*CDIM;
constexpr long ARENA_SZ = OFF_W2 + (long)CDIM*MLPH;

__device__ float g_arena[ARENA_SZ];

// ---------------- helpers ----------------
__device__ __forceinline__ uint32_t f2tf32(float f) {
    uint32_t o;
    asm("cvt.rna.tf32.f32 %0, %1;" : "=r"(o) : "f"(f));
    return o;
}
__device__ __forceinline__ float round_tf32(float f) {
    return __uint_as_float(f2tf32(f));
}

__device__ __forceinline__ uint32_t smem_u32(const void* p) {
    uint32_t a;
    asm("{ .reg .u64 t; cvta.to.shared.u64 t, %1; cvt.u32.u64 %0, t; }" : "=r"(a) : "l"(p));
    return a;
}

__device__ __forceinline__ void mma_tf32(float* c, const uint32_t* a, const uint32_t* b) {
    asm volatile(
        "mma.sync.aligned.m16n8k8.row.col.f32.tf32.tf32.f32 "
        "{%0,%1,%2,%3}, {%4,%5,%6,%7}, {%8,%9}, {%0,%1,%2,%3};\n"
        : "+f"(c[0]), "+f"(c[1]), "+f"(c[2]), "+f"(c[3])
        : "r"(a[0]), "r"(a[1]), "r"(a[2]), "r"(a[3]), "r"(b[0]), "r"(b[1]));
}

__device__ __forceinline__ void ldsm_x4(uint32_t* r, uint32_t addr) {
    asm volatile("ldmatrix.sync.aligned.m8n8.x4.shared.b16 {%0,%1,%2,%3}, [%4];"
        : "=r"(r[0]), "=r"(r[1]), "=r"(r[2]), "=r"(r[3]) : "r"(addr));
}
__device__ __forceinline__ void ldsm_x2(uint32_t* r, uint32_t addr) {
    asm volatile("ldmatrix.sync.aligned.m8n8.x2.shared.b16 {%0,%1}, [%2];"
        : "=r"(r[0]), "=r"(r[1]) : "r"(addr));
}

__device__ __forceinline__ void cp16(uint32_t saddr, const float* g) {
    asm volatile("cp.async.cg.shared.global [%0], [%1], 16;" :: "r"(saddr), "l"(g));
}

__device__ __forceinline__ float gelu_f(float v) {
    return 0.5f * v * (1.0f + erff(v * 0.70710678118654752440f));
}

// ---------------- weight tf32 rounding ----------------
__global__ void tf32_round_kernel(const float* __restrict__ src, long dstOff, int n4)
{
    int i = blockIdx.x * 256 + threadIdx.x;
    if (i < n4) {
        float4 v = ((const float4*)src)[i];
        uint4 u = { f2tf32(v.x), f2tf32(v.y), f2tf32(v.z), f2tf32(v.w) };
        ((uint4*)(g_arena + dstOff))[i] = u;
    }
}

// ---------------- layernorm (outputs tf32-rounded; they only feed GEMMs) ----------------
__global__ void ln_kernel(const float* __restrict__ xext, long xOff,
                          const float* __restrict__ w, const float* __restrict__ b,
                          long outOff)
{
    int row = blockIdx.x;
    const float* xr = (xext ? xext : (const float*)(g_arena + xOff)) + (long)row * CDIM;
    int t = threadIdx.x;
    float v0 = xr[t], v1 = xr[t + 256], v2 = xr[t + 512];
    float s = v0 + v1 + v2;

    __shared__ float red[8];
    #pragma unroll
    for (int o = 16; o > 0; o >>= 1) s += __shfl_xor_sync(0xffffffffu, s, o);
    if ((t & 31) == 0) red[t >> 5] = s;
    __syncthreads();
    float tot = red[0]+red[1]+red[2]+red[3]+red[4]+red[5]+red[6]+red[7];
    float mu = tot * (1.0f / CDIM);

    float d0 = v0 - mu, d1 = v1 - mu, d2 = v2 - mu;
    float q = d0*d0 + d1*d1 + d2*d2;
    #pragma unroll
    for (int o = 16; o > 0; o >>= 1) q += __shfl_xor_sync(0xffffffffu, q, o);
    __syncthreads();
    if ((t & 31) == 0) red[t >> 5] = q;
    __syncthreads();
    float qt = red[0]+red[1]+red[2]+red[3]+red[4]+red[5]+red[6]+red[7];
    float inv = rsqrtf(qt * (1.0f / CDIM) + 1e-5f);

    float* op = g_arena + outOff + (long)row * CDIM;
    op[t      ] = round_tf32(d0 * inv * w[t      ] + b[t      ]);
    op[t + 256] = round_tf32(d1 * inv * w[t + 256] + b[t + 256]);
    op[t + 512] = round_tf32(d2 * inv * w[t + 512] + b[t + 512]);
}

// ---------------- TF32 mma.sync GEMM: 2-stage cp.async, 1 barrier/iter ----------------
// 128x128 tile, BK=16, 256 threads (8 warps, 2x4 warp grid, 64x32 warp tile).
// Static smem (40960 B), copy of stage kt+1 overlaps compute of stage kt.
// Loop: [issue kt+1 -> slot^1] [compute slot] [wait 0; sync]  == 1 barrier/iter.
// MODE 0: C = acc;  MODE 2: C = round_tf32(gelu(acc+bias));  MODE 3: C = res+acc+bias (Cext)
#define RSTR 20                       // row stride in words
#define STAGE_B (128 * RSTR * 4)      // bytes per buffer per operand

template<int MODE>
__global__ __launch_bounds__(256, 2)
void mma_gemm(long aOff, long wOff, long cOff, float* __restrict__ Cext,
              const float* __restrict__ bias, long resOff,
              int K, int Nout, long aStride, long wStride, long cStride)
{
    const float* A = g_arena + aOff + (long)blockIdx.z * aStride;
    const float* W = g_arena + wOff + (long)blockIdx.z * wStride;
    float* Cp = Cext ? Cext : (g_arena + cOff + (long)blockIdx.z * cStride);

    int m0 = blockIdx.y * 128;
    int n0 = blockIdx.x * 128;
    int tid = threadIdx.x, lane = tid & 31, wid = tid >> 5;
    int wm = (wid & 1) * 64;
    int wn = (wid >> 1) * 32;
    int g = lane >> 2, tg = lane & 3;

    __shared__ uint32_t As[2][128][RSTR];
    __shared__ uint32_t Bs[2][128][RSTR];
    uint32_t sbA = smem_u32(As);
    uint32_t sbB = smem_u32(Bs);

    // ldmatrix per-lane row addresses (within a stage)
    int r8 = lane & 7, t4 = lane >> 3;
    uint32_t a_base = sbA + (uint32_t)(((wm + r8 + (t4 & 1) * 8) * RSTR + (t4 >> 1) * 4) * 4);
    uint32_t b_base = sbB + (uint32_t)(((wn + r8) * RSTR + (t4 & 1) * 4) * 4);

    float c[4][4][4] = {};

    // gmem->smem: row = tid&127, two 16B chunks at words q0 and q0+8 (q0 = (tid>>7)*4)
    int lrow = tid & 127;
    int q0 = (tid >> 7) * 4;
    const float* arow = &A[(long)(m0 + lrow) * K + q0];
    const float* brow = &W[(long)(n0 + lrow) * K + q0];
    uint32_t sa = sbA + (uint32_t)((lrow * RSTR + q0) * 4);
    uint32_t sb = sbB + (uint32_t)((lrow * RSTR + q0) * 4);

    int nk = K >> 4;

    // prologue: stage 0 -> slot 0
    cp16(sa, arow);       cp16(sa + 32, arow + 8);
    cp16(sb, brow);       cp16(sb + 32, brow + 8);
    asm volatile("cp.async.commit_group;" ::: "memory");
    asm volatile("cp.async.wait_group 0;" ::: "memory");
    __syncthreads();

    int buf = 0;
    for (int kt = 0; kt < nk; ++kt) {
        // issue stage kt+1 into slot^1 — its readers (compute at kt-1) finished
        // before the sync that ended iteration kt-1.
        if (kt + 1 < nk) {
            uint32_t off = (uint32_t)((buf ^ 1) * STAGE_B);
            const float* an = arow + (kt + 1) * 16;
            const float* bn = brow + (kt + 1) * 16;
            cp16(sa + off, an);       cp16(sa + off + 32, an + 8);
            cp16(sb + off, bn);       cp16(sb + off + 32, bn + 8);
            asm volatile("cp.async.commit_group;" ::: "memory");
        }

        // compute stage kt (copy of kt+1 overlaps these 32 MMAs)
        uint32_t abuf = a_base + (uint32_t)(buf * STAGE_B);
        uint32_t bbuf = b_base + (uint32_t)(buf * STAGE_B);
        #pragma unroll
        for (int ks = 0; ks < 2; ks++) {
            uint32_t af[4][4];
            #pragma unroll
            for (int mt = 0; mt < 4; mt++)
                ldsm_x4(af[mt], abuf + mt * (16 * RSTR * 4) + ks * 32);
            uint32_t bfr[4][2];
            #pragma unroll
            for (int nt = 0; nt < 4; nt++)
                ldsm_x2(bfr[nt], bbuf + nt * (8 * RSTR * 4) + ks * 32);
            #pragma unroll
            for (int mt = 0; mt < 4; mt++)
                #pragma unroll
                for (int nt = 0; nt < 4; nt++)
                    mma_tf32(c[mt][nt], af[mt], bfr[nt]);
        }

        // publish stage kt+1 and protect slot reuse: one barrier per iteration
        if (kt + 1 < nk) {
            asm volatile("cp.async.wait_group 0;" ::: "memory");
            __syncthreads();
        }
        buf ^= 1;
    }

    // epilogue: c[mt][nt]: rows m0+wm+mt*16+g(+8), cols n0+wn+nt*8+tg*2(+1)
    #pragma unroll
    for (int mt = 0; mt < 4; mt++) {
        #pragma unroll
        for (int half = 0; half < 2; half++) {
            long row = m0 + wm + mt * 16 + g + half * 8;
            #pragma unroll
            for (int nt = 0; nt < 4; nt++) {
                int col = n0 + wn + nt * 8 + tg * 2;
                float v0 = c[mt][nt][half * 2 + 0];
                float v1 = c[mt][nt][half * 2 + 1];
                if (MODE == 2) {
                    v0 = round_tf32(gelu_f(v0 + bias[col]));
                    v1 = round_tf32(gelu_f(v1 + bias[col + 1]));
                } else if (MODE == 3) {
                    float2 r = *(const float2*)&g_arena[resOff + row * (long)Nout + col];
                    v0 = r.x + v0 + bias[col];
                    v1 = r.y + v1 + bias[col + 1];
                }
                float2 o; o.x = v0; o.y = v1;
                *(float2*)&Cp[row * (long)Nout + col] = o;
            }
        }
    }
}

// ---------------- tensor-core flash attention (unchanged from R8 passing) ----------------
#define ATK 32

__global__ __launch_bounds__(128)
void attn_mma_kernel()
{
    int z = blockIdx.z;
    int b = z & 7;
    int stage = z >> 3;
    int hh = blockIdx.y;
    int q0 = blockIdx.x * 128;
    int tid = threadIdx.x;
    int warp = tid >> 5, lane = tid & 31;
    int g = lane >> 2, tg = lane & 3;

    const float* qbase = g_arena + OFF_QKV + (long)(b * NSEQ) * QKVW + stage * 2304 + hh * HDIM;
    const float* kbase = qbase + CDIM;
    const float* vbase = qbase + 2 * CDIM;

    __shared__ uint32_t Ks[ATK][68];
    __shared__ uint32_t Vs[ATK][72];
    __shared__ uint32_t Ps[4][32][36];

    uint32_t qa[2][8][4];
    int mrow = q0 + warp * 32;
    #pragma unroll
    for (int mt = 0; mt < 2; mt++) {
        #pragma unroll
        for (int ks = 0; ks < 8; ks++) {
            const float* r0 = qbase + (long)(mrow + mt * 16 + g) * QKVW + ks * 8 + tg;
            const float* r1 = r0 + 8 * QKVW;
            qa[mt][ks][0] = f2tf32(0.125f * __ldg(r0));
            qa[mt][ks][1] = f2tf32(0.125f * __ldg(r1));
            qa[mt][ks][2] = f2tf32(0.125f * __ldg(r0 + 4));
            qa[mt][ks][3] = f2tf32(0.125f * __ldg(r1 + 4));
        }
    }

    float o[2][8][4] = {};
    float mr[4] = {-1e30f, -1e30f, -1e30f, -1e30f};
    float lr[4] = {0.f, 0.f, 0.f, 0.f};

    for (int k0 = 0; k0 < NSEQ; k0 += ATK) {
        __syncthreads();
        {
            int row = tid & 31, cs = tid >> 5;
            const float* kp = kbase + (long)(k0 + row) * QKVW + cs * 16;
            const float* vp = vbase + (long)(k0 + row) * QKVW + cs * 16;
            #pragma unroll
            for (int j = 0; j < 4; j++) {
                float4 kv = *(const float4*)(kp + j * 4);
                float4 vv = *(const float4*)(vp + j * 4);
                int cb = cs * 16 + j * 4;
                Ks[row][cb+0] = f2tf32(kv.x); Ks[row][cb+1] = f2tf32(kv.y);
                Ks[row][cb+2] = f2tf32(kv.z); Ks[row][cb+3] = f2tf32(kv.w);
                Vs[row][cb+0] = f2tf32(vv.x); Vs[row][cb+1] = f2tf32(vv.y);
                Vs[row][cb+2] = f2tf32(vv.z); Vs[row][cb+3] = f2tf32(vv.w);
            }
        }
        __syncthreads();

        float c[2][4][4] = {};
        #pragma unroll
        for (int ks = 0; ks < 8; ks++) {
            uint32_t kb_[4][2];
            #pragma unroll
            for (int nt = 0; nt < 4; nt++) {
                kb_[nt][0] = Ks[nt * 8 + g][ks * 8 + tg];
                kb_[nt][1] = Ks[nt * 8 + g][ks * 8 + tg + 4];
            }
            #pragma unroll
            for (int mt = 0; mt < 2; mt++)
                #pragma unroll
                for (int nt = 0; nt < 4; nt++)
                    mma_tf32(c[mt][nt], qa[mt][ks], kb_[nt]);
        }

        float tm[4] = {-1e30f, -1e30f, -1e30f, -1e30f};
        #pragma unroll
        for (int mt = 0; mt < 2; mt++)
            #pragma unroll
            for (int nt = 0; nt < 4; nt++)
                #pragma unroll
                for (int r = 0; r < 4; r++)
                    tm[mt * 2 + (r >> 1)] = fmaxf(tm[mt * 2 + (r >> 1)], c[mt][nt][r]);
        #pragma unroll
        for (int i = 0; i < 4; i++) {
            tm[i] = fmaxf(tm[i], __shfl_xor_sync(0xffffffffu, tm[i], 1));
            tm[i] = fmaxf(tm[i], __shfl_xor_sync(0xffffffffu, tm[i], 2));
        }
        float mn[4], corr[4];
        #pragma unroll
        for (int i = 0; i < 4; i++) {
            mn[i] = fmaxf(mr[i], tm[i]);
            corr[i] = __expf(mr[i] - mn[i]);
        }
        float ts[4] = {0.f, 0.f, 0.f, 0.f};
        #pragma unroll
        for (int mt = 0; mt < 2; mt++)
            #pragma unroll
            for (int nt = 0; nt < 4; nt++)
                #pragma unroll
                for (int r = 0; r < 4; r++) {
                    int i = mt * 2 + (r >> 1);
                    float p = __expf(c[mt][nt][r] - mn[i]);
                    c[mt][nt][r] = p;
                    ts[i] += p;
                }
        #pragma unroll
        for (int i = 0; i < 4; i++) {
            ts[i] += __shfl_xor_sync(0xffffffffu, ts[i], 1);
            ts[i] += __shfl_xor_sync(0xffffffffu, ts[i], 2);
            lr[i] = lr[i] * corr[i] + ts[i];
            mr[i] = mn[i];
        }
        #pragma unroll
        for (int mt = 0; mt < 2; mt++)
            #pragma unroll
            for (int nd = 0; nd < 8; nd++)
                #pragma unroll
                for (int r = 0; r < 4; r++)
                    o[mt][nd][r] *= corr[mt * 2 + (r >> 1)];

        #pragma unroll
        for (int mt = 0; mt < 2; mt++)
            #pragma unroll
            for (int nt = 0; nt < 4; nt++) {
                int r0 = mt * 16 + g, col = nt * 8 + tg * 2;
                uint2 p0, p1;
                p0.x = f2tf32(c[mt][nt][0]); p0.y = f2tf32(c[mt][nt][1]);
                p1.x = f2tf32(c[mt][nt][2]); p1.y = f2tf32(c[mt][nt][3]);
                *(uint2*)&Ps[warp][r0][col]     = p0;
                *(uint2*)&Ps[warp][r0 + 8][col] = p1;
            }
        __syncwarp();

        #pragma unroll
        for (int kk = 0; kk < 4; kk++) {
            uint32_t pa[2][4];
            #pragma unroll
            for (int mt = 0; mt < 2; mt++) {
                pa[mt][0] = Ps[warp][mt * 16 + g]    [kk * 8 + tg];
                pa[mt][1] = Ps[warp][mt * 16 + 8 + g][kk * 8 + tg];
                pa[mt][2] = Ps[warp][mt * 16 + g]    [kk * 8 + tg + 4];
                pa[mt][3] = Ps[warp][mt * 16 + 8 + g][kk * 8 + tg + 4];
            }
            uint32_t vb[8][2];
            #pragma unroll
            for (int nd = 0; nd < 8; nd++) {
                vb[nd][0] = Vs[kk * 8 + tg]    [nd * 8 + g];
                vb[nd][1] = Vs[kk * 8 + tg + 4][nd * 8 + g];
            }
            #pragma unroll
            for (int mt = 0; mt < 2; mt++)
                #pragma unroll
                for (int nd = 0; nd < 8; nd++)
                    mma_tf32(o[mt][nd], pa[mt], vb[nd]);
        }
        __syncwarp();
    }

    float inv[4];
    #pragma unroll
    for (int i = 0; i < 4; i++) inv[i] = 1.0f / lr[i];

    #pragma unroll
    for (int mt = 0; mt < 2; mt++) {
        #pragma unroll
        for (int half = 0; half < 2; half++) {
            long row = (long)stage * TOK + (long)b * NSEQ + mrow + mt * 16 + g + half * 8;
            float sc = inv[mt * 2 + half];
            float* op = g_arena + OFF_O + row * CDIM + hh * HDIM;
            #pragma unroll
            for (int nd = 0; nd < 8; nd++) {
                float2 v;
                v.x = round_tf32(o[mt][nd][half * 2 + 0] * sc);
                v.y = round_tf32(o[mt][nd][half * 2 + 1] * sc);
                *(float2*)&op[nd * 8 + tg * 2] = v;
            }
        }
    }
}

// ---------------- combine: x1 = x + sum_i fw[i]*(p_i + proj_b_i) ----------------
__global__ void combine_kernel(const float* __restrict__ x, const float* __restrict__ pb,
                               const float* __restrict__ fw)
{
    long idx = (long)blockIdx.x * 256 + threadIdx.x;
    int c = (int)(idx % CDIM);
    const float* p = g_arena + OFF_P;
    float f0 = __ldg(&fw[0]), f1 = __ldg(&fw[1]), f2 = __ldg(&fw[2]);
    float v = x[idx];
    v = fmaf(f0, p[idx]           + pb[c],            v);
    v = fmaf(f1, p[TOKC + idx]    + pb[CDIM + c],     v);
    v = fmaf(f2, p[2*TOKC + idx]  + pb[2*CDIM + c],   v);
    g_arena[OFF_X1 + idx] = v;
}

// ---------------- launch ----------------
extern "C" void kernel_launch(void* const* d_in, const int* in_sizes, int n_in,
                              void* d_out, int out_size)
{
    const float* x      = (const float*)d_in[0];
    const float* qkv_w  = (const float*)d_in[1];
    const float* proj_w = (const float*)d_in[2];
    const float* proj_b = (const float*)d_in[3];
    const float* ln1_w  = (const float*)d_in[4];
    const float* ln1_b  = (const float*)d_in[5];
    const float* ln2_w  = (const float*)d_in[6];
    const float* ln2_b  = (const float*)d_in[7];
    const float* mlp_w1 = (const float*)d_in[8];
    const float* mlp_b1 = (const float*)d_in[9];
    const float* mlp_w2 = (const float*)d_in[10];
    const float* mlp_b2 = (const float*)d_in[11];
    const float* fw     = (const float*)d_in[12];
    float* out = (float*)d_out;

    // 0) round weights to tf32 into arena copies
    tf32_round_kernel<<<(QKVW*CDIM/4 + 255)/256, 256>>>(qkv_w, OFF_WQ, QKVW*CDIM/4);
    tf32_round_kernel<<<(STAGES*CDIM*CDIM/4 + 255)/256, 256>>>(proj_w, OFF_WP, STAGES*CDIM*CDIM/4);
    tf32_round_kernel<<<(MLPH*CDIM/4 + 255)/256, 256>>>(mlp_w1, OFF_W1, MLPH*CDIM/4);
    tf32_round_kernel<<<(CDIM*MLPH/4 + 255)/256, 256>>>(mlp_w2, OFF_W2, CDIM*MLPH/4);

    // 1) h = LN1(x)  (tf32-rounded)
    ln_kernel<<<TOK, 256>>>(x, 0, ln1_w, ln1_b, OFF_H);

    // 2) qkv(all stages) = h @ qkv_w_all^T   [8192 x 6912]
    mma_gemm<0><<<dim3(QKVW / 128, TOK / 128, 1), 256>>>(
        OFF_H, OFF_WQ, OFF_QKV, nullptr, nullptr, 0, CDIM, QKVW, 0, 0, 0);

    // 3) attention, all stages (tensor-core)
    attn_mma_kernel<<<dim3(NSEQ / 128, HNUM, STAGES * BATCH), 128>>>();

    // 4) p_i = o_i @ proj_w_i^T (batched over stage)
    mma_gemm<0><<<dim3(CDIM / 128, TOK / 128, STAGES), 256>>>(
        OFF_O, OFF_WP, OFF_P, nullptr, nullptr, 0, CDIM, CDIM,
        TOKC, (long)CDIM * CDIM, TOKC);

    // 5) x1 = x + sum_i fw[i]*(p_i + proj_b_i)
    combine_kernel<<<(int)(TOKC / 256), 256>>>(x, proj_b, fw);

    // 6) h2 = LN2(x1)  (tf32-rounded)
    ln_kernel<<<TOK, 256>>>(nullptr, OFF_X1, ln2_w, ln2_b, OFF_H2);

    // 7) g = gelu(h2 @ mlp_w1^T + b1)   [8192 x 3072]  (tf32-rounded)
    mma_gemm<2><<<dim3(MLPH / 128, TOK / 128, 1), 256>>>(
        OFF_H2, OFF_W1, OFF_G, nullptr, mlp_b1, 0, CDIM, MLPH, 0, 0, 0);

    // 8) out = x1 + g @ mlp_w2^T + b2
    mma_gemm<3><<<dim3(CDIM / 128, TOK / 128, 1), 256>>>(
        OFF_G, OFF_W2, 0, out, mlp_b2, OFF_X1, MLPH, CDIM, 0, 0, 0);
}

// round 12
// speedup vs baseline: 4.0107x; 1.6523x over previous
#include <cuda_runtime.h>
#include <cuda_fp16.h>
#include <math.h>
#include <stdint.h>

// ---------------- problem constants ----------------
#define TOK    8192        // B*N
#define CDIM   768
#define HNUM   12
#define HDIM   64
#define NSEQ   1024
#define BATCH  8
#define MLPH   3072
#define QKVW   6912        // 3 stages * 3*C
#define STAGES 3

constexpr long TOKC   = (long)TOK * CDIM;
// fp32 arena: QKV, P, X1
constexpr long OFF_QKV = 0;
constexpr long OFF_P   = OFF_QKV + (long)TOK*QKVW;
constexpr long OFF_X1  = OFF_P   + 3*TOKC;
constexpr long ARENA_SZ = OFF_X1 + TOKC;

__device__ float g_arena[ARENA_SZ];

// fp16 arena: activations + weights feeding GEMMs
constexpr long HOFF_H   = 0;                         // LN1 out [TOK, C]
constexpr long HOFF_O   = HOFF_H  + TOKC;            // attn out [3, TOK, C]
constexpr long HOFF_H2  = HOFF_O  + 3*TOKC;          // LN2 out [TOK, C]
constexpr long HOFF_G   = HOFF_H2 + TOKC;            // gelu out [TOK, MLPH]
constexpr long HOFF_WQ  = HOFF_G  + (long)TOK*MLPH;
constexpr long HOFF_WP  = HOFF_WQ + (long)QKVW*CDIM;
constexpr long HOFF_W1  = HOFF_WP + (long)STAGES*CDIM*CDIM;
constexpr long HOFF_W2  = HOFF_W1 + (long)MLPH*CDIM;
constexpr long HARENA_SZ = HOFF_W2 + (long)CDIM*MLPH;

__device__ __half h_arena[HARENA_SZ];

// ---------------- helpers ----------------
__device__ __forceinline__ uint32_t f2tf32(float f) {
    uint32_t o;
    asm("cvt.rna.tf32.f32 %0, %1;" : "=r"(o) : "f"(f));
    return o;
}

__device__ __forceinline__ uint32_t smem_u32(const void* p) {
    uint32_t a;
    asm("{ .reg .u64 t; cvta.to.shared.u64 t, %1; cvt.u32.u64 %0, t; }" : "=r"(a) : "l"(p));
    return a;
}

// tf32 k8 mma (attention, unchanged)
__device__ __forceinline__ void mma_tf32(float* c, const uint32_t* a, const uint32_t* b) {
    asm volatile(
        "mma.sync.aligned.m16n8k8.row.col.f32.tf32.tf32.f32 "
        "{%0,%1,%2,%3}, {%4,%5,%6,%7}, {%8,%9}, {%0,%1,%2,%3};\n"
        : "+f"(c[0]), "+f"(c[1]), "+f"(c[2]), "+f"(c[3])
        : "r"(a[0]), "r"(a[1]), "r"(a[2]), "r"(a[3]), "r"(b[0]), "r"(b[1]));
}

// fp16 k16 mma, fp32 accumulate (GEMMs)
__device__ __forceinline__ void mma_f16(float* c, const uint32_t* a, const uint32_t* b) {
    asm volatile(
        "mma.sync.aligned.m16n8k16.row.col.f32.f16.f16.f32 "
        "{%0,%1,%2,%3}, {%4,%5,%6,%7}, {%8,%9}, {%0,%1,%2,%3};\n"
        : "+f"(c[0]), "+f"(c[1]), "+f"(c[2]), "+f"(c[3])
        : "r"(a[0]), "r"(a[1]), "r"(a[2]), "r"(a[3]), "r"(b[0]), "r"(b[1]));
}

__device__ __forceinline__ void ldsm_x4(uint32_t* r, uint32_t addr) {
    asm volatile("ldmatrix.sync.aligned.m8n8.x4.shared.b16 {%0,%1,%2,%3}, [%4];"
        : "=r"(r[0]), "=r"(r[1]), "=r"(r[2]), "=r"(r[3]) : "r"(addr));
}
__device__ __forceinline__ void ldsm_x2(uint32_t* r, uint32_t addr) {
    asm volatile("ldmatrix.sync.aligned.m8n8.x2.shared.b16 {%0,%1}, [%2];"
        : "=r"(r[0]), "=r"(r[1]) : "r"(addr));
}

__device__ __forceinline__ void cp16(uint32_t saddr, const void* g) {
    asm volatile("cp.async.cg.shared.global [%0], [%1], 16;" :: "r"(saddr), "l"(g));
}

__device__ __forceinline__ float gelu_f(float v) {
    return 0.5f * v * (1.0f + erff(v * 0.70710678118654752440f));
}

// ---------------- weight fp16 rounding ----------------
__global__ void f16_round_kernel(const float* __restrict__ src, long dstOff, int n4)
{
    int i = blockIdx.x * 256 + threadIdx.x;
    if (i < n4) {
        float4 v = ((const float4*)src)[i];
        __half2 lo = __floats2half2_rn(v.x, v.y);
        __half2 hi = __floats2half2_rn(v.z, v.w);
        ((__half2*)(h_arena + dstOff))[i * 2]     = lo;
        ((__half2*)(h_arena + dstOff))[i * 2 + 1] = hi;
    }
}

// ---------------- layernorm (fp16 output; only feeds GEMMs) ----------------
__global__ void ln_kernel(const float* __restrict__ xext, long xOff,
                          const float* __restrict__ w, const float* __restrict__ b,
                          long outOffH)
{
    int row = blockIdx.x;
    const float* xr = (xext ? xext : (const float*)(g_arena + xOff)) + (long)row * CDIM;
    int t = threadIdx.x;
    float v0 = xr[t], v1 = xr[t + 256], v2 = xr[t + 512];
    float s = v0 + v1 + v2;

    __shared__ float red[8];
    #pragma unroll
    for (int o = 16; o > 0; o >>= 1) s += __shfl_xor_sync(0xffffffffu, s, o);
    if ((t & 31) == 0) red[t >> 5] = s;
    __syncthreads();
    float tot = red[0]+red[1]+red[2]+red[3]+red[4]+red[5]+red[6]+red[7];
    float mu = tot * (1.0f / CDIM);

    float d0 = v0 - mu, d1 = v1 - mu, d2 = v2 - mu;
    float q = d0*d0 + d1*d1 + d2*d2;
    #pragma unroll
    for (int o = 16; o > 0; o >>= 1) q += __shfl_xor_sync(0xffffffffu, q, o);
    __syncthreads();
    if ((t & 31) == 0) red[t >> 5] = q;
    __syncthreads();
    float qt = red[0]+red[1]+red[2]+red[3]+red[4]+red[5]+red[6]+red[7];
    float inv = rsqrtf(qt * (1.0f / CDIM) + 1e-5f);

    __half* op = h_arena + outOffH + (long)row * CDIM;
    op[t      ] = __float2half_rn(d0 * inv * w[t      ] + b[t      ]);
    op[t + 256] = __float2half_rn(d1 * inv * w[t + 256] + b[t + 256]);
    op[t + 512] = __float2half_rn(d2 * inv * w[t + 512] + b[t + 512]);
}

// ---------------- FP16 mma.sync GEMM: 2-stage cp.async, 1 barrier/iter ----------------
// 128x128 tile, BK=16 (one k16 MMA per frag pair), 256 threads, 8 warps (2x4, 64x32/warp).
// Smem: halfs, row = 16 halfs (32B), row stride 24 halfs (48B; 3 chunks of 16B -> ldmatrix
// conflict-free since 3r mod 8 is a bijection over 8 rows). 2 stages x 2 operands x 6KB = 24KB.
// MODE 0: fp32 C = acc (g_arena/cOff);  MODE 2: half C = gelu(acc+bias) (h_arena/cOff);
// MODE 3: fp32 C = res + acc + bias (Cext)
#define RSH  24                        // row stride in halfs
#define STAGE_HB (128 * RSH * 2)       // bytes per operand-stage = 6144

template<int MODE>
__global__ __launch_bounds__(256, 2)
void mma_gemm(long aOff, long wOff, long cOff, float* __restrict__ Cext,
              const float* __restrict__ bias, long resOff,
              int K, int Nout, long aStride, long wStride, long cStride)
{
    const __half* A = h_arena + aOff + (long)blockIdx.z * aStride;
    const __half* W = h_arena + wOff + (long)blockIdx.z * wStride;

    int m0 = blockIdx.y * 128;
    int n0 = blockIdx.x * 128;
    int tid = threadIdx.x, lane = tid & 31, wid = tid >> 5;
    int wm = (wid & 1) * 64;
    int wn = (wid >> 1) * 32;
    int g = lane >> 2, tg = lane & 3;

    __shared__ __half As[2][128 * RSH];
    __shared__ __half Bs[2][128 * RSH];
    uint32_t sbA = smem_u32(As);
    uint32_t sbB = smem_u32(Bs);

    // ldmatrix per-lane addresses: A x4 -> mats {m,k-lo},{m+8,k-lo},{m,k-hi},{m+8,k-hi}
    int r8 = lane & 7, t4 = lane >> 3;
    uint32_t a_base = sbA + (uint32_t)((wm + r8 + (t4 & 1) * 8) * 48 + (t4 >> 1) * 16);
    // B x2 -> mats {n rows, k-lo},{n rows, k-hi} (lanes 0-15 used)
    uint32_t b_base = sbB + (uint32_t)((wn + r8) * 48 + (t4 & 1) * 16);

    float c[4][4][4] = {};

    // gmem->smem: 128 rows x 2 chunks(16B) per operand; thread t: row=t>>1, chunk=t&1
    int lrow = tid >> 1;
    int chk = tid & 1;
    const __half* arow = &A[(long)(m0 + lrow) * K + chk * 8];
    const __half* brow = &W[(long)(n0 + lrow) * K + chk * 8];
    uint32_t sa = sbA + (uint32_t)(lrow * 48 + chk * 16);
    uint32_t sb = sbB + (uint32_t)(lrow * 48 + chk * 16);

    int nk = K >> 4;

    // prologue: stage 0 -> slot 0
    cp16(sa, arow);
    cp16(sb, brow);
    asm volatile("cp.async.commit_group;" ::: "memory");
    asm volatile("cp.async.wait_group 0;" ::: "memory");
    __syncthreads();

    int buf = 0;
    for (int kt = 0; kt < nk; ++kt) {
        if (kt + 1 < nk) {
            uint32_t off = (uint32_t)((buf ^ 1) * STAGE_HB);
            cp16(sa + off, arow + (kt + 1) * 16);
            cp16(sb + off, brow + (kt + 1) * 16);
            asm volatile("cp.async.commit_group;" ::: "memory");
        }

        uint32_t abuf = a_base + (uint32_t)(buf * STAGE_HB);
        uint32_t bbuf = b_base + (uint32_t)(buf * STAGE_HB);
        uint32_t af[4][4];
        #pragma unroll
        for (int mt = 0; mt < 4; mt++)
            ldsm_x4(af[mt], abuf + mt * (16 * 48));
        uint32_t bfr[4][2];
        #pragma unroll
        for (int nt = 0; nt < 4; nt++)
            ldsm_x2(bfr[nt], bbuf + nt * (8 * 48));
        #pragma unroll
        for (int mt = 0; mt < 4; mt++)
            #pragma unroll
            for (int nt = 0; nt < 4; nt++)
                mma_f16(c[mt][nt], af[mt], bfr[nt]);

        if (kt + 1 < nk) {
            asm volatile("cp.async.wait_group 0;" ::: "memory");
            __syncthreads();
        }
        buf ^= 1;
    }

    // epilogue: c[mt][nt]: rows m0+wm+mt*16+g(+8), cols n0+wn+nt*8+tg*2(+1)
    #pragma unroll
    for (int mt = 0; mt < 4; mt++) {
        #pragma unroll
        for (int half = 0; half < 2; half++) {
            long row = m0 + wm + mt * 16 + g + half * 8;
            #pragma unroll
            for (int nt = 0; nt < 4; nt++) {
                int col = n0 + wn + nt * 8 + tg * 2;
                float v0 = c[mt][nt][half * 2 + 0];
                float v1 = c[mt][nt][half * 2 + 1];
                if (MODE == 2) {
                    v0 = gelu_f(v0 + bias[col]);
                    v1 = gelu_f(v1 + bias[col + 1]);
                    *(__half2*)&h_arena[cOff + row * (long)Nout + col] = __floats2half2_rn(v0, v1);
                } else if (MODE == 3) {
                    float2 r = *(const float2*)&g_arena[resOff + row * (long)Nout + col];
                    float2 o;
                    o.x = r.x + v0 + bias[col];
                    o.y = r.y + v1 + bias[col + 1];
                    *(float2*)&Cext[row * (long)Nout + col] = o;
                } else {
                    float2 o; o.x = v0; o.y = v1;
                    *(float2*)&g_arena[cOff + (long)blockIdx.z * cStride + row * (long)Nout + col] = o;
                }
            }
        }
    }
}

// ---------------- tensor-core flash attention (tf32 core unchanged; fp16 output) ----------------
#define ATK 32

__global__ __launch_bounds__(128)
void attn_mma_kernel()
{
    int z = blockIdx.z;
    int b = z & 7;
    int stage = z >> 3;
    int hh = blockIdx.y;
    int q0 = blockIdx.x * 128;
    int tid = threadIdx.x;
    int warp = tid >> 5, lane = tid & 31;
    int g = lane >> 2, tg = lane & 3;

    const float* qbase = g_arena + OFF_QKV + (long)(b * NSEQ) * QKVW + stage * 2304 + hh * HDIM;
    const float* kbase = qbase + CDIM;
    const float* vbase = qbase + 2 * CDIM;

    __shared__ uint32_t Ks[ATK][68];
    __shared__ uint32_t Vs[ATK][72];
    __shared__ uint32_t Ps[4][32][36];

    uint32_t qa[2][8][4];
    int mrow = q0 + warp * 32;
    #pragma unroll
    for (int mt = 0; mt < 2; mt++) {
        #pragma unroll
        for (int ks = 0; ks < 8; ks++) {
            const float* r0 = qbase + (long)(mrow + mt * 16 + g) * QKVW + ks * 8 + tg;
            const float* r1 = r0 + 8 * QKVW;
            qa[mt][ks][0] = f2tf32(0.125f * __ldg(r0));
            qa[mt][ks][1] = f2tf32(0.125f * __ldg(r1));
            qa[mt][ks][2] = f2tf32(0.125f * __ldg(r0 + 4));
            qa[mt][ks][3] = f2tf32(0.125f * __ldg(r1 + 4));
        }
    }

    float o[2][8][4] = {};
    float mr[4] = {-1e30f, -1e30f, -1e30f, -1e30f};
    float lr[4] = {0.f, 0.f, 0.f, 0.f};

    for (int k0 = 0; k0 < NSEQ; k0 += ATK) {
        __syncthreads();
        {
            int row = tid & 31, cs = tid >> 5;
            const float* kp = kbase + (long)(k0 + row) * QKVW + cs * 16;
            const float* vp = vbase + (long)(k0 + row) * QKVW + cs * 16;
            #pragma unroll
            for (int j = 0; j < 4; j++) {
                float4 kv = *(const float4*)(kp + j * 4);
                float4 vv = *(const float4*)(vp + j * 4);
                int cb = cs * 16 + j * 4;
                Ks[row][cb+0] = f2tf32(kv.x); Ks[row][cb+1] = f2tf32(kv.y);
                Ks[row][cb+2] = f2tf32(kv.z); Ks[row][cb+3] = f2tf32(kv.w);
                Vs[row][cb+0] = f2tf32(vv.x); Vs[row][cb+1] = f2tf32(vv.y);
                Vs[row][cb+2] = f2tf32(vv.z); Vs[row][cb+3] = f2tf32(vv.w);
            }
        }
        __syncthreads();

        float c[2][4][4] = {};
        #pragma unroll
        for (int ks = 0; ks < 8; ks++) {
            uint32_t kb_[4][2];
            #pragma unroll
            for (int nt = 0; nt < 4; nt++) {
                kb_[nt][0] = Ks[nt * 8 + g][ks * 8 + tg];
                kb_[nt][1] = Ks[nt * 8 + g][ks * 8 + tg + 4];
            }
            #pragma unroll
            for (int mt = 0; mt < 2; mt++)
                #pragma unroll
                for (int nt = 0; nt < 4; nt++)
                    mma_tf32(c[mt][nt], qa[mt][ks], kb_[nt]);
        }

        float tm[4] = {-1e30f, -1e30f, -1e30f, -1e30f};
        #pragma unroll
        for (int mt = 0; mt < 2; mt++)
            #pragma unroll
            for (int nt = 0; nt < 4; nt++)
                #pragma unroll
                for (int r = 0; r < 4; r++)
                    tm[mt * 2 + (r >> 1)] = fmaxf(tm[mt * 2 + (r >> 1)], c[mt][nt][r]);
        #pragma unroll
        for (int i = 0; i < 4; i++) {
            tm[i] = fmaxf(tm[i], __shfl_xor_sync(0xffffffffu, tm[i], 1));
            tm[i] = fmaxf(tm[i], __shfl_xor_sync(0xffffffffu, tm[i], 2));
        }
        float mn[4], corr[4];
        #pragma unroll
        for (int i = 0; i < 4; i++) {
            mn[i] = fmaxf(mr[i], tm[i]);
            corr[i] = __expf(mr[i] - mn[i]);
        }
        float ts[4] = {0.f, 0.f, 0.f, 0.f};
        #pragma unroll
        for (int mt = 0; mt < 2; mt++)
            #pragma unroll
            for (int nt = 0; nt < 4; nt++)
                #pragma unroll
                for (int r = 0; r < 4; r++) {
                    int i = mt * 2 + (r >> 1);
                    float p = __expf(c[mt][nt][r] - mn[i]);
                    c[mt][nt][r] = p;
                    ts[i] += p;
                }
        #pragma unroll
        for (int i = 0; i < 4; i++) {
            ts[i] += __shfl_xor_sync(0xffffffffu, ts[i], 1);
            ts[i] += __shfl_xor_sync(0xffffffffu, ts[i], 2);
            lr[i] = lr[i] * corr[i] + ts[i];
            mr[i] = mn[i];
        }
        #pragma unroll
        for (int mt = 0; mt < 2; mt++)
            #pragma unroll
            for (int nd = 0; nd < 8; nd++)
                #pragma unroll
                for (int r = 0; r < 4; r++)
                    o[mt][nd][r] *= corr[mt * 2 + (r >> 1)];

        #pragma unroll
        for (int mt = 0; mt < 2; mt++)
            #pragma unroll
            for (int nt = 0; nt < 4; nt++) {
                int r0 = mt * 16 + g, col = nt * 8 + tg * 2;
                uint2 p0, p1;
                p0.x = f2tf32(c[mt][nt][0]); p0.y = f2tf32(c[mt][nt][1]);
                p1.x = f2tf32(c[mt][nt][2]); p1.y = f2tf32(c[mt][nt][3]);
                *(uint2*)&Ps[warp][r0][col]     = p0;
                *(uint2*)&Ps[warp][r0 + 8][col] = p1;
            }
        __syncwarp();

        #pragma unroll
        for (int kk = 0; kk < 4; kk++) {
            uint32_t pa[2][4];
            #pragma unroll
            for (int mt = 0; mt < 2; mt++) {
                pa[mt][0] = Ps[warp][mt * 16 + g]    [kk * 8 + tg];
                pa[mt][1] = Ps[warp][mt * 16 + 8 + g][kk * 8 + tg];
                pa[mt][2] = Ps[warp][mt * 16 + g]    [kk * 8 + tg + 4];
                pa[mt][3] = Ps[warp][mt * 16 + 8 + g][kk * 8 + tg + 4];
            }
            uint32_t vb[8][2];
            #pragma unroll
            for (int nd = 0; nd < 8; nd++) {
                vb[nd][0] = Vs[kk * 8 + tg]    [nd * 8 + g];
                vb[nd][1] = Vs[kk * 8 + tg + 4][nd * 8 + g];
            }
            #pragma unroll
            for (int mt = 0; mt < 2; mt++)
                #pragma unroll
                for (int nd = 0; nd < 8; nd++)
                    mma_tf32(o[mt][nd], pa[mt], vb[nd]);
        }
        __syncwarp();
    }

    float inv[4];
    #pragma unroll
    for (int i = 0; i < 4; i++) inv[i] = 1.0f / lr[i];

    // fp16 output (feeds proj GEMM)
    #pragma unroll
    for (int mt = 0; mt < 2; mt++) {
        #pragma unroll
        for (int half = 0; half < 2; half++) {
            long row = (long)stage * TOK + (long)b * NSEQ + mrow + mt * 16 + g + half * 8;
            float sc = inv[mt * 2 + half];
            __half* op = h_arena + HOFF_O + row * CDIM + hh * HDIM;
            #pragma unroll
            for (int nd = 0; nd < 8; nd++) {
                float x0 = o[mt][nd][half * 2 + 0] * sc;
                float x1 = o[mt][nd][half * 2 + 1] * sc;
                *(__half2*)&op[nd * 8 + tg * 2] = __floats2half2_rn(x0, x1);
            }
        }
    }
}

// ---------------- combine: x1 = x + sum_i fw[i]*(p_i + proj_b_i) ----------------
__global__ void combine_kernel(const float* __restrict__ x, const float* __restrict__ pb,
                               const float* __restrict__ fw)
{
    long idx = (long)blockIdx.x * 256 + threadIdx.x;
    int c = (int)(idx % CDIM);
    const float* p = g_arena + OFF_P;
    float f0 = __ldg(&fw[0]), f1 = __ldg(&fw[1]), f2 = __ldg(&fw[2]);
    float v = x[idx];
    v = fmaf(f0, p[idx]           + pb[c],            v);
    v = fmaf(f1, p[TOKC + idx]    + pb[CDIM + c],     v);
    v = fmaf(f2, p[2*TOKC + idx]  + pb[2*CDIM + c],   v);
    g_arena[OFF_X1 + idx] = v;
}

// ---------------- launch ----------------
extern "C" void kernel_launch(void* const* d_in, const int* in_sizes, int n_in,
                              void* d_out, int out_size)
{
    const float* x      = (const float*)d_in[0];
    const float* qkv_w  = (const float*)d_in[1];
    const float* proj_w = (const float*)d_in[2];
    const float* proj_b = (const float*)d_in[3];
    const float* ln1_w  = (const float*)d_in[4];
    const float* ln1_b  = (const float*)d_in[5];
    const float* ln2_w  = (const float*)d_in[6];
    const float* ln2_b  = (const float*)d_in[7];
    const float* mlp_w1 = (const float*)d_in[8];
    const float* mlp_b1 = (const float*)d_in[9];
    const float* mlp_w2 = (const float*)d_in[10];
    const float* mlp_b2 = (const float*)d_in[11];
    const float* fw     = (const float*)d_in[12];
    float* out = (float*)d_out;

    // 0) round weights to fp16 into half-arena copies
    f16_round_kernel<<<(QKVW*CDIM/4 + 255)/256, 256>>>(qkv_w, HOFF_WQ, QKVW*CDIM/4);
    f16_round_kernel<<<(STAGES*CDIM*CDIM/4 + 255)/256, 256>>>(proj_w, HOFF_WP, STAGES*CDIM*CDIM/4);
    f16_round_kernel<<<(MLPH*CDIM/4 + 255)/256, 256>>>(mlp_w1, HOFF_W1, MLPH*CDIM/4);
    f16_round_kernel<<<(CDIM*MLPH/4 + 255)/256, 256>>>(mlp_w2, HOFF_W2, CDIM*MLPH/4);

    // 1) h = LN1(x)  (fp16)
    ln_kernel<<<TOK, 256>>>(x, 0, ln1_w, ln1_b, HOFF_H);

    // 2) qkv(all stages) = h @ qkv_w_all^T   [8192 x 6912]  (fp32 out)
    mma_gemm<0><<<dim3(QKVW / 128, TOK / 128, 1), 256>>>(
        HOFF_H, HOFF_WQ, OFF_QKV, nullptr, nullptr, 0, CDIM, QKVW, 0, 0, 0);

    // 3) attention, all stages (tf32 core, fp16 out)
    attn_mma_kernel<<<dim3(NSEQ / 128, HNUM, STAGES * BATCH), 128>>>();

    // 4) p_i = o_i @ proj_w_i^T (batched over stage; fp32 out)
    mma_gemm<0><<<dim3(CDIM / 128, TOK / 128, STAGES), 256>>>(
        HOFF_O, HOFF_WP, OFF_P, nullptr, nullptr, 0, CDIM, CDIM,
        TOKC, (long)CDIM * CDIM, TOKC);

    // 5) x1 = x + sum_i fw[i]*(p_i + proj_b_i)
    combine_kernel<<<(int)(TOKC / 256), 256>>>(x, proj_b, fw);

    // 6) h2 = LN2(x1)  (fp16)
    ln_kernel<<<TOK, 256>>>(nullptr, OFF_X1, ln2_w, ln2_b, HOFF_H2);

    // 7) g = gelu(h2 @ mlp_w1^T + b1)   [8192 x 3072]  (fp16 out)
    mma_gemm<2><<<dim3(MLPH / 128, TOK / 128, 1), 256>>>(
        HOFF_H2, HOFF_W1, HOFF_G, nullptr, mlp_b1, 0, CDIM, MLPH, 0, 0, 0);

    // 8) out = x1 + g @ mlp_w2^T + b2   (fp32 out with residual)
    mma_gemm<3><<<dim3(CDIM / 128, TOK / 128, 1), 256>>>(
        HOFF_G, HOFF_W2, 0, out, mlp_b2, OFF_X1, MLPH, CDIM, 0, 0, 0);
}